// round 14
// baseline (speedup 1.0000x reference)
#include <cuda_runtime.h>
#include <cuda_fp16.h>
#include <mma.h>
#include <math.h>

using namespace nvcuda;

#define DIMV       512
#define HEADS      8
#define DIM_KEY    32
#define NUM_KEYS   256
#define QCOLS      256
#define TOPK       16
#define TOKENS     1024
#define FULLMASK   0xffffffffu

// scratch (device globals; no allocs)
__device__ __align__(16) float  g_q   [TOKENS * QCOLS];    // exact q, cols 0..255
__device__ __align__(16) __half g_qh  [TOKENS * DIMV];     // fp16 q, all cols
__device__ __align__(16) float  g_sim [HEADS * TOKENS * NUM_KEYS];
__device__ __align__(16) __half g_wdTh[DIMV * NUM_KEYS];
__device__ __align__(16) float  g_D   [TOKENS * NUM_KEYS];
__device__ __align__(16) __half g_Sh  [TOKENS * NUM_KEYS];

// ---------------------------------------------------------------------------
// PDL helpers
// ---------------------------------------------------------------------------
__device__ __forceinline__ void pdl_trigger() {
    asm volatile("griddepcontrol.launch_dependents;" ::: "memory");
}
__device__ __forceinline__ void pdl_wait() {
    asm volatile("griddepcontrol.wait;" ::: "memory");
}

// ---------------------------------------------------------------------------
// helpers
// ---------------------------------------------------------------------------
__device__ __forceinline__ uint4 pack8h(float4 f0, float4 f1) {
    __half2 h0 = __floats2half2_rn(f0.x, f0.y);
    __half2 h1 = __floats2half2_rn(f0.z, f0.w);
    __half2 h2 = __floats2half2_rn(f1.x, f1.y);
    __half2 h3 = __floats2half2_rn(f1.z, f1.w);
    uint4 u;
    u.x = *reinterpret_cast<unsigned*>(&h0);
    u.y = *reinterpret_cast<unsigned*>(&h1);
    u.z = *reinterpret_cast<unsigned*>(&h2);
    u.w = *reinterpret_cast<unsigned*>(&h3);
    return u;
}

__device__ __forceinline__ void split8(const float* p, uint4& hi, uint4& lo) {
    float4 f0 = *reinterpret_cast<const float4*>(p);
    float4 f1 = *reinterpret_cast<const float4*>(p + 4);
    float v[8] = {f0.x, f0.y, f0.z, f0.w, f1.x, f1.y, f1.z, f1.w};
    __align__(16) __half h[8];
    __align__(16) __half l[8];
#pragma unroll
    for (int i = 0; i < 8; i++) {
        h[i] = __float2half_rn(v[i]);
        l[i] = __float2half_rn(v[i] - __half2float(h[i]));
    }
    hi = *reinterpret_cast<uint4*>(h);
    lo = *reinterpret_cast<uint4*>(l);
}

// ---------------------------------------------------------------------------
// K4: out = Sh @ wup[:256] — single-shot HMMA, K=256.
// B staged from fp32 wup (input) BEFORE pdl_wait; A (g_Sh) after.
// smem: As[64][264] + Bs[256][72] = 70656B (dynamic)
// ---------------------------------------------------------------------------
#define SS_SMEM_BYTES (64*264*2 + 256*72*2)

__global__ void __launch_bounds__(256)
k4_gemm(const float* __restrict__ wup, float* __restrict__ out)
{
    extern __shared__ __align__(16) char dsmem[];
    __half (*As)[264] = (__half(*)[264])dsmem;
    __half (*Bs)[72]  = (__half(*)[72])(dsmem + 64 * 264 * 2);

    pdl_trigger();

    const int tid = threadIdx.x;
    const int w = tid >> 5;
    const int wm = w >> 1;
    const int wn = w & 1;
    int bid = blockIdx.x;
    int m0 = (bid >> 3) * 64;
    int n0 = (bid & 7) * 64;

    // prologue: stage B tile from fp32 wup (pure input) with inline convert
#pragma unroll
    for (int i = 0; i < 8; i++) {
        int u = tid + i * 256;
        int row = u >> 3;               // 0..255
        int c8 = (u & 7) * 8;           // 0..56
        const float* b = wup + (size_t)row * DIMV + n0 + c8;
        *reinterpret_cast<uint4*>(&Bs[row][c8]) =
            pack8h(*reinterpret_cast<const float4*>(b),
                   *reinterpret_cast<const float4*>(b + 4));
    }

    pdl_wait();   // select (and transitively all predecessors) complete

    // stage A from g_Sh
#pragma unroll
    for (int i = 0; i < 2; i++) {
        int u = tid + i * 256;
        int row = u >> 3;               // 0..63 (8 uint4 per 256-half row)
        int c8 = (u & 7) * 32;          // 0,32,...,224  -> 4 uint4 each
#pragma unroll
        for (int j = 0; j < 4; j++)
            *reinterpret_cast<uint4*>(&As[row][c8 + j * 8]) =
                *reinterpret_cast<const uint4*>(
                    g_Sh + (size_t)(m0 + row) * NUM_KEYS + c8 + j * 8);
    }
    __syncthreads();

    wmma::fragment<wmma::accumulator, 16, 16, 16, float> acc[2];
    wmma::fill_fragment(acc[0], 0.0f);
    wmma::fill_fragment(acc[1], 0.0f);

    wmma::fragment<wmma::matrix_a, 16, 16, 16, __half, wmma::row_major> af;
    wmma::fragment<wmma::matrix_b, 16, 16, 16, __half, wmma::row_major> bf;
#pragma unroll
    for (int ks = 0; ks < 16; ks++) {
        wmma::load_matrix_sync(af, &As[wm * 16][ks * 16], 264);
#pragma unroll
        for (int i = 0; i < 2; i++) {
            wmma::load_matrix_sync(bf, &Bs[ks * 16][wn * 32 + i * 16], 72);
            wmma::mma_sync(acc[i], af, bf, acc[i]);
        }
    }

#pragma unroll
    for (int i = 0; i < 2; i++) {
        wmma::store_matrix_sync(
            &out[(size_t)(m0 + wm * 16) * DIMV + n0 + wn * 32 + i * 16],
            acc[i], DIMV, wmma::mem_row_major);
    }
}

// ---------------------------------------------------------------------------
// fp16 WMMA GEMM, double-buffered BK=32 (G2, K=512): 64x64 tile, half inputs.
// smem: As[2][64][40] + Bs[2][32][72] = 19456B
// ---------------------------------------------------------------------------
#define HGEMM_SMEM_BYTES (2*64*40*2 + 2*32*72*2)

template<int K, int NTOT>
__device__ __forceinline__ void hgemm_db(
    const __half* __restrict__ Av, const __half* __restrict__ Bv,
    float* __restrict__ C, int m0, int n0, char* smem_raw)
{
    typedef __half AsT[64][40];
    typedef __half BsT[32][72];
    AsT* As = (AsT*)smem_raw;
    BsT* Bs = (BsT*)(smem_raw + 2 * 64 * 40 * 2);

    const int tid = threadIdx.x;
    const int w = tid >> 5;
    const int wm = w >> 1;
    const int wn = w & 1;

    const int arow = tid >> 2;
    const int akq  = (tid & 3) * 8;
    const int brow = tid >> 3;
    const int bnq  = (tid & 7) * 8;

    wmma::fragment<wmma::accumulator, 16, 16, 16, float> acc[2];
    wmma::fill_fragment(acc[0], 0.0f);
    wmma::fill_fragment(acc[1], 0.0f);

    uint4 areg = *reinterpret_cast<const uint4*>(
        Av + (size_t)(m0 + arow) * K + akq);
    uint4 breg = *reinterpret_cast<const uint4*>(
        Bv + (size_t)brow * NTOT + n0 + bnq);

    int buf = 0;
    const int NT = K / 32;
#pragma unroll 1
    for (int kt = 0; kt < NT; kt++) {
        *reinterpret_cast<uint4*>(&As[buf][arow][akq]) = areg;
        *reinterpret_cast<uint4*>(&Bs[buf][brow][bnq]) = breg;
        __syncthreads();

        if (kt + 1 < NT) {
            int k0 = (kt + 1) * 32;
            areg = *reinterpret_cast<const uint4*>(
                Av + (size_t)(m0 + arow) * K + k0 + akq);
            breg = *reinterpret_cast<const uint4*>(
                Bv + (size_t)(k0 + brow) * NTOT + n0 + bnq);
        }

        wmma::fragment<wmma::matrix_a, 16, 16, 16, __half, wmma::row_major> af;
        wmma::fragment<wmma::matrix_b, 16, 16, 16, __half, wmma::row_major> bf;
#pragma unroll
        for (int ks = 0; ks < 2; ks++) {
            wmma::load_matrix_sync(af, &As[buf][wm * 16][ks * 16], 40);
#pragma unroll
            for (int i = 0; i < 2; i++) {
                wmma::load_matrix_sync(bf, &Bs[buf][ks * 16][wn * 32 + i * 16], 72);
                wmma::mma_sync(acc[i], af, bf, acc[i]);
            }
        }
        buf ^= 1;
    }

#pragma unroll
    for (int i = 0; i < 2; i++) {
        wmma::store_matrix_sync(
            &C[(size_t)(m0 + wm * 16) * NTOT + n0 + wn * 32 + i * 16],
            acc[i], NTOT, wmma::mem_row_major);
    }
}

// ---------------------------------------------------------------------------
// G1a: split fp16 GEMM (xh*wh + xh*wl + xl*wh) for q cols 0..255.
// ---------------------------------------------------------------------------
#define K1_SMEM_BYTES (10240 + 10240 + 9216 + 9216)

__device__ __forceinline__ void g1_split_gemm(
    const float* __restrict__ x, const float* __restrict__ wq,
    int m0, int n0, char* smem_raw)
{
    typedef __half A_t[64][40];
    typedef __half B_t[32][72];
    A_t* Ah = (A_t*)smem_raw;
    A_t* Al = (A_t*)(smem_raw + 10240);
    B_t* Bh = (B_t*)(smem_raw + 20480);
    B_t* Bl = (B_t*)(smem_raw + 29696);

    const int tid = threadIdx.x;
    const int w = tid >> 5;
    const int wm = w >> 1;
    const int wn = w & 1;

    const int arow = tid >> 2;
    const int akq  = (tid & 3) * 8;
    const int brow = tid >> 3;
    const int bnq  = (tid & 7) * 8;

    wmma::fragment<wmma::accumulator, 16, 16, 16, float> acc[2];
    wmma::fill_fragment(acc[0], 0.0f);
    wmma::fill_fragment(acc[1], 0.0f);

    uint4 ah, al, bh, bl;
    split8(&x [(size_t)(m0 + arow) * DIMV + akq], ah, al);
    split8(&wq[(size_t)brow * DIMV + n0 + bnq], bh, bl);

    int buf = 0;
    const int NT = DIMV / 32;
#pragma unroll 1
    for (int kt = 0; kt < NT; kt++) {
        *reinterpret_cast<uint4*>(&Ah[buf][arow][akq]) = ah;
        *reinterpret_cast<uint4*>(&Al[buf][arow][akq]) = al;
        *reinterpret_cast<uint4*>(&Bh[buf][brow][bnq]) = bh;
        *reinterpret_cast<uint4*>(&Bl[buf][brow][bnq]) = bl;
        __syncthreads();

        if (kt + 1 < NT) {
            int k0 = (kt + 1) * 32;
            split8(&x [(size_t)(m0 + arow) * DIMV + k0 + akq], ah, al);
            split8(&wq[(size_t)(k0 + brow) * DIMV + n0 + bnq], bh, bl);
        }

        wmma::fragment<wmma::matrix_a, 16, 16, 16, __half, wmma::row_major> afh, afl;
        wmma::fragment<wmma::matrix_b, 16, 16, 16, __half, wmma::row_major> bfh, bfl;
#pragma unroll
        for (int ks = 0; ks < 2; ks++) {
            wmma::load_matrix_sync(afh, &Ah[buf][wm * 16][ks * 16], 40);
            wmma::load_matrix_sync(afl, &Al[buf][wm * 16][ks * 16], 40);
#pragma unroll
            for (int i = 0; i < 2; i++) {
                wmma::load_matrix_sync(bfh, &Bh[buf][ks * 16][wn * 32 + i * 16], 72);
                wmma::load_matrix_sync(bfl, &Bl[buf][ks * 16][wn * 32 + i * 16], 72);
                wmma::mma_sync(acc[i], afh, bfh, acc[i]);
                wmma::mma_sync(acc[i], afh, bfl, acc[i]);
                wmma::mma_sync(acc[i], afl, bfh, acc[i]);
            }
        }
        buf ^= 1;
    }

    __syncthreads();
    float (*Cs)[68] = (float(*)[68])smem_raw;
#pragma unroll
    for (int i = 0; i < 2; i++)
        wmma::store_matrix_sync(&Cs[wm * 16][wn * 32 + i * 16], acc[i], 68,
                                wmma::mem_row_major);
    __syncthreads();

    const float scale = 0.99999500003749981f;
    int trow = tid >> 2;
    int tc0  = (tid & 3) * 16;
    float4 fo[4];
#pragma unroll
    for (int j = 0; j < 4; j++) {
        float4 f = *reinterpret_cast<const float4*>(&Cs[trow][tc0 + j * 4]);
        f.x *= scale; f.y *= scale; f.z *= scale; f.w *= scale;
        fo[j] = f;
        *reinterpret_cast<float4*>(
            &g_q[(size_t)(m0 + trow) * QCOLS + n0 + tc0 + j * 4]) = f;
    }
    uint4 hq0 = pack8h(fo[0], fo[1]);
    uint4 hq1 = pack8h(fo[2], fo[3]);
    __half* qh = &g_qh[(size_t)(m0 + trow) * DIMV + n0 + tc0];
    *reinterpret_cast<uint4*>(qh)     = hq0;
    *reinterpret_cast<uint4*>(qh + 8) = hq1;
}

// ---------------------------------------------------------------------------
// G1b: plain fp16 GEMM for q cols 256..511 -> g_qh only.
// ---------------------------------------------------------------------------
__device__ __forceinline__ void g1_plain_gemm(
    const float* __restrict__ x, const float* __restrict__ wq,
    int m0, int n0, char* smem_raw)
{
    typedef __half AsT[64][40];
    typedef __half BsT[32][72];
    AsT* As = (AsT*)smem_raw;
    BsT* Bs = (BsT*)(smem_raw + 2 * 64 * 40 * 2);

    const int tid = threadIdx.x;
    const int w = tid >> 5;
    const int wm = w >> 1;
    const int wn = w & 1;

    const int arow = tid >> 2;
    const int akq  = (tid & 3) * 8;
    const int brow = tid >> 3;
    const int bnq  = (tid & 7) * 8;

    wmma::fragment<wmma::accumulator, 16, 16, 16, float> acc[2];
    wmma::fill_fragment(acc[0], 0.0f);
    wmma::fill_fragment(acc[1], 0.0f);

    uint4 areg, breg;
    {
        const float* a = &x[(size_t)(m0 + arow) * DIMV + akq];
        areg = pack8h(*reinterpret_cast<const float4*>(a),
                      *reinterpret_cast<const float4*>(a + 4));
        const float* b = &wq[(size_t)brow * DIMV + n0 + bnq];
        breg = pack8h(*reinterpret_cast<const float4*>(b),
                      *reinterpret_cast<const float4*>(b + 4));
    }

    int buf = 0;
    const int NT = DIMV / 32;
#pragma unroll 1
    for (int kt = 0; kt < NT; kt++) {
        *reinterpret_cast<uint4*>(&As[buf][arow][akq]) = areg;
        *reinterpret_cast<uint4*>(&Bs[buf][brow][bnq]) = breg;
        __syncthreads();

        if (kt + 1 < NT) {
            int k0 = (kt + 1) * 32;
            const float* a = &x[(size_t)(m0 + arow) * DIMV + k0 + akq];
            areg = pack8h(*reinterpret_cast<const float4*>(a),
                          *reinterpret_cast<const float4*>(a + 4));
            const float* b = &wq[(size_t)(k0 + brow) * DIMV + n0 + bnq];
            breg = pack8h(*reinterpret_cast<const float4*>(b),
                          *reinterpret_cast<const float4*>(b + 4));
        }

        wmma::fragment<wmma::matrix_a, 16, 16, 16, __half, wmma::row_major> af;
        wmma::fragment<wmma::matrix_b, 16, 16, 16, __half, wmma::row_major> bf;
#pragma unroll
        for (int ks = 0; ks < 2; ks++) {
            wmma::load_matrix_sync(af, &As[buf][wm * 16][ks * 16], 40);
#pragma unroll
            for (int i = 0; i < 2; i++) {
                wmma::load_matrix_sync(bf, &Bs[buf][ks * 16][wn * 32 + i * 16], 72);
                wmma::mma_sync(acc[i], af, bf, acc[i]);
            }
        }
        buf ^= 1;
    }

    __syncthreads();
    float (*Cs)[68] = (float(*)[68])smem_raw;
#pragma unroll
    for (int i = 0; i < 2; i++)
        wmma::store_matrix_sync(&Cs[wm * 16][wn * 32 + i * 16], acc[i], 68,
                                wmma::mem_row_major);
    __syncthreads();

    const float scale = 0.99999500003749981f;
    int trow = tid >> 2;
    int tc0  = (tid & 3) * 16;
    float4 fo[4];
#pragma unroll
    for (int j = 0; j < 4; j++) {
        float4 f = *reinterpret_cast<const float4*>(&Cs[trow][tc0 + j * 4]);
        f.x *= scale; f.y *= scale; f.z *= scale; f.w *= scale;
        fo[j] = f;
    }
    uint4 hq0 = pack8h(fo[0], fo[1]);
    uint4 hq1 = pack8h(fo[2], fo[3]);
    __half* qh = &g_qh[(size_t)(m0 + trow) * DIMV + n0 + tc0];
    *reinterpret_cast<uint4*>(qh)     = hq0;
    *reinterpret_cast<uint4*>(qh + 8) = hq1;
}

// ---------------------------------------------------------------------------
// K1: 0..63 split GEMM; 64..127 plain GEMM; 128..255 transpose wdown->half.
// No pdl_wait: writes are disjoint from previous replay's k4 reads.
// ---------------------------------------------------------------------------
__global__ void __launch_bounds__(256)
k1_fused(const float* __restrict__ x, const float* __restrict__ wq,
         const float* __restrict__ wdown)
{
    __shared__ __align__(16) char smem[K1_SMEM_BYTES];
    pdl_trigger();
    int bid = blockIdx.x;
    if (bid < 64) {
        int mb = bid >> 2, nb = bid & 3;
        g1_split_gemm(x, wq, mb * 64, nb * 64, smem);
    } else if (bid < 128) {
        int b = bid - 64;
        int mb = b >> 2, nb = b & 3;
        g1_plain_gemm(x, wq, mb * 64, 256 + nb * 64, smem);
    } else {
        int b = bid - 128;
        int d0 = (b & 15) * 32;
        int e0 = (b >> 4) * 32;
        float (*t)[33] = (float(*)[33])smem;
        int tx = threadIdx.x & 31, ty = threadIdx.x >> 5;
#pragma unroll
        for (int i = 0; i < 4; i++)
            t[ty + i * 8][tx] = wdown[(size_t)(e0 + ty + i * 8) * DIMV + d0 + tx];
        __syncthreads();
#pragma unroll
        for (int i = 0; i < 4; i++)
            g_wdTh[(size_t)(d0 + ty + i * 8) * NUM_KEYS + e0 + tx] =
                __float2half_rn(t[tx][ty + i * 8]);
    }
}

// ---------------------------------------------------------------------------
// K2: 0..63 G2 (D = qh @ wdTh); 64..191 sim. Keys staged pre-wait.
// ---------------------------------------------------------------------------
#define SIM_SMEM_BYTES (DIM_KEY*NUM_KEYS*4 + DIM_KEY*64*4)
#define K2_SMEM (SIM_SMEM_BYTES > HGEMM_SMEM_BYTES ? SIM_SMEM_BYTES : HGEMM_SMEM_BYTES)

__global__ void __launch_bounds__(256)
k2_fused(const float* __restrict__ keys)
{
    __shared__ __align__(16) char smem[K2_SMEM];
    pdl_trigger();
    int bid = blockIdx.x;
    int tid = threadIdx.x;

    if (bid < 64) {
        pdl_wait();
        int mb = bid >> 2, nb = bid & 3;
        hgemm_db<DIMV, NUM_KEYS>(g_qh, g_wdTh, g_D, mb * 64, nb * 64, smem);
        return;
    }

    // sim: 128 blocks, (64 tokens x 256 keys) per head
    int b = bid - 64;
    int t0 = (b & 15) * 64;
    int h = b >> 4;

    float (*Ks)[NUM_KEYS] = (float(*)[NUM_KEYS])smem;
    float (*Qs)[64] = (float(*)[64])(smem + DIM_KEY * NUM_KEYS * 4);

    // prologue: keys is a kernel input -> safe before wait
    {
        const float4* kp = reinterpret_cast<const float4*>(
            keys + (size_t)((h * NUM_KEYS + tid) * 2) * DIM_KEY);
#pragma unroll
        for (int i = 0; i < 8; i++) {
            float4 f = kp[i];
            Ks[4 * i + 0][tid] = f.x;
            Ks[4 * i + 1][tid] = f.y;
            Ks[4 * i + 2][tid] = f.z;
            Ks[4 * i + 3][tid] = f.w;
        }
    }

    pdl_wait();   // g_q ready

    {
        int tl = tid & 63;
        int d0 = (tid >> 6) * 8;
        size_t off = (size_t)(t0 + tl) * QCOLS + h * DIM_KEY + d0;
        float4 f0 = *reinterpret_cast<const float4*>(g_q + off);
        float4 f1 = *reinterpret_cast<const float4*>(g_q + off + 4);
        Qs[d0 + 0][tl] = f0.x; Qs[d0 + 1][tl] = f0.y;
        Qs[d0 + 2][tl] = f0.z; Qs[d0 + 3][tl] = f0.w;
        Qs[d0 + 4][tl] = f1.x; Qs[d0 + 5][tl] = f1.y;
        Qs[d0 + 6][tl] = f1.z; Qs[d0 + 7][tl] = f1.w;
    }
    __syncthreads();

    int kg = tid & 15;
    int tg = tid >> 4;
    float acc[4][16];
#pragma unroll
    for (int i = 0; i < 4; i++)
#pragma unroll
        for (int j = 0; j < 16; j++) acc[i][j] = 0.0f;

#pragma unroll
    for (int d = 0; d < DIM_KEY; d++) {
        float4 qv = *reinterpret_cast<const float4*>(&Qs[d][tg * 4]);
        float q4[4] = {qv.x, qv.y, qv.z, qv.w};
        float kv[16];
#pragma unroll
        for (int jj = 0; jj < 4; jj++) {
            float4 kk = *reinterpret_cast<const float4*>(&Ks[d][kg * 16 + jj * 4]);
            kv[jj * 4 + 0] = kk.x; kv[jj * 4 + 1] = kk.y;
            kv[jj * 4 + 2] = kk.z; kv[jj * 4 + 3] = kk.w;
        }
#pragma unroll
        for (int i = 0; i < 4; i++)
#pragma unroll
            for (int j = 0; j < 16; j++) acc[i][j] += q4[i] * kv[j];
    }

#pragma unroll
    for (int i = 0; i < 4; i++) {
        int t = t0 + tg * 4 + i;
        float* op = g_sim + ((size_t)h * TOKENS + t) * NUM_KEYS + kg * 16;
#pragma unroll
        for (int jj = 0; jj < 4; jj++) {
            float4 f;
            f.x = acc[i][jj * 4 + 0]; f.y = acc[i][jj * 4 + 1];
            f.z = acc[i][jj * 4 + 2]; f.w = acc[i][jj * 4 + 3];
            *reinterpret_cast<float4*>(op + jj * 4) = f;
        }
    }
}

// ---------------------------------------------------------------------------
// K3: selection with structural fast path.
// ---------------------------------------------------------------------------
__device__ __forceinline__ float gelu_tanh(float x) {
    float x3 = x * x * x;
    float t = tanhf(0.7978845608028654f * (x + 0.044715f * x3));
    return 0.5f * x * (1.0f + t);
}

__device__ __forceinline__ void warp_top16(float* val, int lane,
                                           float* out_v, int* out_i)
{
#pragma unroll
    for (int r = 0; r < TOPK; r++) {
        float bv = val[0]; int bs = 0;
#pragma unroll
        for (int s = 1; s < 8; s++)
            if (val[s] > bv) { bv = val[s]; bs = s; }
        int bp = lane + (bs << 5);
#pragma unroll
        for (int off = 16; off > 0; off >>= 1) {
            float ov = __shfl_xor_sync(FULLMASK, bv, off);
            int   op = __shfl_xor_sync(FULLMASK, bp, off);
            if (ov > bv || (ov == bv && op < bp)) { bv = ov; bp = op; }
        }
        out_v[r] = bv;
        out_i[r] = bp;
        if ((bp & 31) == lane) {
            int ws = bp >> 5;
#pragma unroll
            for (int s = 0; s < 8; s++)
                if (s == ws) val[s] = -INFINITY;
        }
    }
}

__global__ void __launch_bounds__(256) select_kernel()
{
    int t = blockIdx.x;
    int tid = threadIdx.x;
    int w = tid >> 5;
    int lane = tid & 31;

    __shared__ float sS[NUM_KEYS];
    __shared__ float v0s[HEADS][TOPK];
    __shared__ float i0s[HEADS][TOPK];

    pdl_trigger();
    sS[tid] = 0.0f;
    __syncthreads();

    pdl_wait();   // g_sim, g_D ready

    float val[8];
    {
        const float* simrow = g_sim + ((size_t)w * TOKENS + t) * NUM_KEYS;
#pragma unroll
        for (int s = 0; s < 8; s++)
            val[s] = simrow[lane + (s << 5)];
    }

    float v0[TOPK]; int i0[TOPK];
    warp_top16(val, lane, v0, i0);

    int imax = -1, i2nd = -1, jst = 0;
#pragma unroll
    for (int j = 0; j < TOPK; j++) {
        int v = i0[j];
        if (v > imax) { i2nd = imax; imax = v; jst = j; }
        else if (v > i2nd) i2nd = v;
    }
    float spread = v0[0] - v0[TOPK - 1];
    bool fast = (float)(imax - i2nd) > spread;

    if (fast) {
        float myv = -INFINITY;
#pragma unroll
        for (int r = 0; r < TOPK; r++)
            if (lane == r) myv = v0[r];
        float mye = expf(myv - v0[0]);
        float esum = mye;
#pragma unroll
        for (int off = 16; off > 0; off >>= 1)
            esum += __shfl_xor_sync(FULLMASK, esum, off);
        if (lane < TOPK) {
            int pk = lane * TOPK + jst;
            float dv = g_D[(size_t)t * NUM_KEYS + pk];
            float g = gelu_tanh(dv) * (mye / esum);
            atomicAdd(&sS[pk], g);
        }
    } else {
        if (lane == 0) {
#pragma unroll
            for (int r = 0; r < TOPK; r++) {
                v0s[w][r] = v0[r];
                i0s[w][r] = (float)i0[r];
            }
        }
        __syncwarp();
        float val2[8];
#pragma unroll
        for (int s = 0; s < 8; s++) {
            int p = lane + (s << 5);
            val2[s] = v0s[w][p >> 4] + i0s[w][p & 15];
        }
        float scf[TOPK]; int pk[TOPK];
        warp_top16(val2, lane, scf, pk);

        float myscf = -INFINITY; int mypk = 0;
#pragma unroll
        for (int r = 0; r < TOPK; r++)
            if (lane == r) { myscf = scf[r]; mypk = pk[r]; }
        float m = scf[0];
#pragma unroll
        for (int r = 1; r < TOPK; r++) m = fmaxf(m, scf[r]);
        float mye = expf(myscf - m);
        float esum = mye;
#pragma unroll
        for (int off = 16; off > 0; off >>= 1)
            esum += __shfl_xor_sync(FULLMASK, esum, off);
        if (lane < TOPK) {
            float dv = g_D[(size_t)t * NUM_KEYS + mypk];
            float g = gelu_tanh(dv) * (mye / esum);
            atomicAdd(&sS[mypk], g);
        }
    }
    __syncthreads();

    g_Sh[(size_t)t * NUM_KEYS + tid] = __float2half_rn(sS[tid]);
}

// ---------------------------------------------------------------------------
extern "C" void kernel_launch(void* const* d_in, const int* in_sizes, int n_in,
                              void* d_out, int out_size)
{
    const float* x     = (const float*)d_in[0];
    const float* w_q   = (const float*)d_in[1];
    const float* keys  = (const float*)d_in[2];
    const float* wdown = (const float*)d_in[3];
    const float* wup   = (const float*)d_in[4];
    float* out = (float*)d_out;

    cudaFuncSetAttribute(k4_gemm,
        cudaFuncAttributeMaxDynamicSharedMemorySize, SS_SMEM_BYTES);

    cudaLaunchAttribute attrs[1];
    attrs[0].id = cudaLaunchAttributeProgrammaticStreamSerialization;
    attrs[0].val.programmaticStreamSerializationAllowed = 1;

    {
        cudaLaunchConfig_t cfg = {};
        cfg.gridDim = dim3(256, 1, 1);
        cfg.blockDim = dim3(256, 1, 1);
        cfg.attrs = attrs; cfg.numAttrs = 1;
        cudaLaunchKernelEx(&cfg, k1_fused, x, w_q, wdown);
    }
    {
        cudaLaunchConfig_t cfg = {};
        cfg.gridDim = dim3(192, 1, 1);
        cfg.blockDim = dim3(256, 1, 1);
        cfg.attrs = attrs; cfg.numAttrs = 1;
        cudaLaunchKernelEx(&cfg, k2_fused, keys);
    }
    {
        cudaLaunchConfig_t cfg = {};
        cfg.gridDim = dim3(TOKENS, 1, 1);
        cfg.blockDim = dim3(256, 1, 1);
        cfg.attrs = attrs; cfg.numAttrs = 1;
        cudaLaunchKernelEx(&cfg, select_kernel);
    }
    {
        cudaLaunchConfig_t cfg = {};
        cfg.gridDim = dim3(128, 1, 1);
        cfg.blockDim = dim3(256, 1, 1);
        cfg.dynamicSmemBytes = SS_SMEM_BYTES;
        cfg.attrs = attrs; cfg.numAttrs = 1;
        cudaLaunchKernelEx(&cfg, k4_gemm, wup, out);
    }
}

// round 15
// speedup vs baseline: 1.0114x; 1.0114x over previous
#include <cuda_runtime.h>
#include <cuda_fp16.h>
#include <mma.h>
#include <math.h>

using namespace nvcuda;

#define DIMV       512
#define HEADS      8
#define DIM_KEY    32
#define NUM_KEYS   256
#define QCOLS      256
#define TOPK       16
#define TOKENS     1024
#define NBLOCKS    256
#define FULLMASK   0xffffffffu

// scratch (device globals; no allocs)
__device__ __align__(16) float  g_q   [TOKENS * QCOLS];
__device__ __align__(16) __half g_qh  [TOKENS * DIMV];
__device__ __align__(16) float  g_sim [HEADS * TOKENS * NUM_KEYS];
__device__ __align__(16) __half g_wdTh[DIMV * NUM_KEYS];
__device__ __align__(16) __half g_wupH[NUM_KEYS * DIMV];
__device__ __align__(16) float  g_D   [TOKENS * NUM_KEYS];
__device__ __align__(16) __half g_Sh  [TOKENS * NUM_KEYS];

// software grid barrier state (self-resetting; zero-init at module load)
__device__ volatile unsigned g_cnt[4];
__device__ volatile unsigned g_ack[4];

__device__ __forceinline__ void grid_sync(int k) {
    __syncthreads();
    if (threadIdx.x == 0) {
        __threadfence();
        atomicAdd((unsigned*)&g_cnt[k], 1u);
        while (g_cnt[k] < NBLOCKS) __nanosleep(64);
        __threadfence();
        unsigned a = atomicAdd((unsigned*)&g_ack[k], 1u);
        if (a == NBLOCKS - 1) {       // last one out resets for next replay
            g_cnt[k] = 0;
            __threadfence();
            g_ack[k] = 0;
        }
    }
    __syncthreads();
}

// ---------------------------------------------------------------------------
// helpers
// ---------------------------------------------------------------------------
__device__ __forceinline__ uint4 pack8h(float4 f0, float4 f1) {
    __half2 h0 = __floats2half2_rn(f0.x, f0.y);
    __half2 h1 = __floats2half2_rn(f0.z, f0.w);
    __half2 h2 = __floats2half2_rn(f1.x, f1.y);
    __half2 h3 = __floats2half2_rn(f1.z, f1.w);
    uint4 u;
    u.x = *reinterpret_cast<unsigned*>(&h0);
    u.y = *reinterpret_cast<unsigned*>(&h1);
    u.z = *reinterpret_cast<unsigned*>(&h2);
    u.w = *reinterpret_cast<unsigned*>(&h3);
    return u;
}

__device__ __forceinline__ void split8(const float* p, uint4& hi, uint4& lo) {
    float4 f0 = *reinterpret_cast<const float4*>(p);
    float4 f1 = *reinterpret_cast<const float4*>(p + 4);
    float v[8] = {f0.x, f0.y, f0.z, f0.w, f1.x, f1.y, f1.z, f1.w};
    __align__(16) __half h[8];
    __align__(16) __half l[8];
#pragma unroll
    for (int i = 0; i < 8; i++) {
        h[i] = __float2half_rn(v[i]);
        l[i] = __float2half_rn(v[i] - __half2float(h[i]));
    }
    hi = *reinterpret_cast<uint4*>(h);
    lo = *reinterpret_cast<uint4*>(l);
}

__device__ __forceinline__ float gelu_tanh(float x) {
    float x3 = x * x * x;
    float t = tanhf(0.7978845608028654f * (x + 0.044715f * x3));
    return 0.5f * x * (1.0f + t);
}

__device__ __forceinline__ void warp_top16(float* val, int lane,
                                           float* out_v, int* out_i)
{
#pragma unroll
    for (int r = 0; r < TOPK; r++) {
        float bv = val[0]; int bs = 0;
#pragma unroll
        for (int s = 1; s < 8; s++)
            if (val[s] > bv) { bv = val[s]; bs = s; }
        int bp = lane + (bs << 5);
#pragma unroll
        for (int off = 16; off > 0; off >>= 1) {
            float ov = __shfl_xor_sync(FULLMASK, bv, off);
            int   op = __shfl_xor_sync(FULLMASK, bp, off);
            if (ov > bv || (ov == bv && op < bp)) { bv = ov; bp = op; }
        }
        out_v[r] = bv;
        out_i[r] = bp;
        if ((bp & 31) == lane) {
            int ws = bp >> 5;
#pragma unroll
            for (int s = 0; s < 8; s++)
                if (s == ws) val[s] = -INFINITY;
        }
    }
}

// ---------------------------------------------------------------------------
// shared memory: one 40960B buffer reused across phases
// ---------------------------------------------------------------------------
#define SMEM_BYTES 40960

// ---------------------------------------------------------------------------
// G1a: split fp16 GEMM (xh*wh + xh*wl + xl*wh) for q cols 0..255.
// smem: Ah[2][64][40] Al (10240 each) + Bh[2][32][72] Bl (9216 each) = 38912
// ---------------------------------------------------------------------------
__device__ void g1_split_gemm(
    const float* __restrict__ x, const float* __restrict__ wq,
    int m0, int n0, char* smem_raw)
{
    typedef __half A_t[64][40];
    typedef __half B_t[32][72];
    A_t* Ah = (A_t*)smem_raw;
    A_t* Al = (A_t*)(smem_raw + 10240);
    B_t* Bh = (B_t*)(smem_raw + 20480);
    B_t* Bl = (B_t*)(smem_raw + 29696);

    const int tid = threadIdx.x;
    const int w = tid >> 5;
    const int wm = w >> 1;
    const int wn = w & 1;

    const int arow = tid >> 2;
    const int akq  = (tid & 3) * 8;
    const int brow = tid >> 3;
    const int bnq  = (tid & 7) * 8;

    wmma::fragment<wmma::accumulator, 16, 16, 16, float> acc[2];
    wmma::fill_fragment(acc[0], 0.0f);
    wmma::fill_fragment(acc[1], 0.0f);

    uint4 ah, al, bh, bl;
    split8(&x [(size_t)(m0 + arow) * DIMV + akq], ah, al);
    split8(&wq[(size_t)brow * DIMV + n0 + bnq], bh, bl);

    int buf = 0;
    const int NT = DIMV / 32;
#pragma unroll 1
    for (int kt = 0; kt < NT; kt++) {
        *reinterpret_cast<uint4*>(&Ah[buf][arow][akq]) = ah;
        *reinterpret_cast<uint4*>(&Al[buf][arow][akq]) = al;
        *reinterpret_cast<uint4*>(&Bh[buf][brow][bnq]) = bh;
        *reinterpret_cast<uint4*>(&Bl[buf][brow][bnq]) = bl;
        __syncthreads();

        if (kt + 1 < NT) {
            int k0 = (kt + 1) * 32;
            split8(&x [(size_t)(m0 + arow) * DIMV + k0 + akq], ah, al);
            split8(&wq[(size_t)(k0 + brow) * DIMV + n0 + bnq], bh, bl);
        }

        wmma::fragment<wmma::matrix_a, 16, 16, 16, __half, wmma::row_major> afh, afl;
        wmma::fragment<wmma::matrix_b, 16, 16, 16, __half, wmma::row_major> bfh, bfl;
#pragma unroll
        for (int ks = 0; ks < 2; ks++) {
            wmma::load_matrix_sync(afh, &Ah[buf][wm * 16][ks * 16], 40);
            wmma::load_matrix_sync(afl, &Al[buf][wm * 16][ks * 16], 40);
#pragma unroll
            for (int i = 0; i < 2; i++) {
                wmma::load_matrix_sync(bfh, &Bh[buf][ks * 16][wn * 32 + i * 16], 72);
                wmma::load_matrix_sync(bfl, &Bl[buf][ks * 16][wn * 32 + i * 16], 72);
                wmma::mma_sync(acc[i], afh, bfh, acc[i]);
                wmma::mma_sync(acc[i], afh, bfl, acc[i]);
                wmma::mma_sync(acc[i], afl, bfh, acc[i]);
            }
        }
        buf ^= 1;
    }

    __syncthreads();
    float (*Cs)[68] = (float(*)[68])smem_raw;
#pragma unroll
    for (int i = 0; i < 2; i++)
        wmma::store_matrix_sync(&Cs[wm * 16][wn * 32 + i * 16], acc[i], 68,
                                wmma::mem_row_major);
    __syncthreads();

    const float scale = 0.99999500003749981f;
    int trow = tid >> 2;
    int tc0  = (tid & 3) * 16;
    float4 fo[4];
#pragma unroll
    for (int j = 0; j < 4; j++) {
        float4 f = *reinterpret_cast<const float4*>(&Cs[trow][tc0 + j * 4]);
        f.x *= scale; f.y *= scale; f.z *= scale; f.w *= scale;
        fo[j] = f;
        *reinterpret_cast<float4*>(
            &g_q[(size_t)(m0 + trow) * QCOLS + n0 + tc0 + j * 4]) = f;
    }
    uint4 hq0 = pack8h(fo[0], fo[1]);
    uint4 hq1 = pack8h(fo[2], fo[3]);
    __half* qh = &g_qh[(size_t)(m0 + trow) * DIMV + n0 + tc0];
    *reinterpret_cast<uint4*>(qh)     = hq0;
    *reinterpret_cast<uint4*>(qh + 8) = hq1;
}

// ---------------------------------------------------------------------------
// G1b: plain fp16 GEMM for q cols 256..511 -> g_qh only. smem 19456B.
// ---------------------------------------------------------------------------
__device__ void g1_plain_gemm(
    const float* __restrict__ x, const float* __restrict__ wq,
    int m0, int n0, char* smem_raw)
{
    typedef __half AsT[64][40];
    typedef __half BsT[32][72];
    AsT* As = (AsT*)smem_raw;
    BsT* Bs = (BsT*)(smem_raw + 2 * 64 * 40 * 2);

    const int tid = threadIdx.x;
    const int w = tid >> 5;
    const int wm = w >> 1;
    const int wn = w & 1;

    const int arow = tid >> 2;
    const int akq  = (tid & 3) * 8;
    const int brow = tid >> 3;
    const int bnq  = (tid & 7) * 8;

    wmma::fragment<wmma::accumulator, 16, 16, 16, float> acc[2];
    wmma::fill_fragment(acc[0], 0.0f);
    wmma::fill_fragment(acc[1], 0.0f);

    uint4 areg, breg;
    {
        const float* a = &x[(size_t)(m0 + arow) * DIMV + akq];
        areg = pack8h(*reinterpret_cast<const float4*>(a),
                      *reinterpret_cast<const float4*>(a + 4));
        const float* b = &wq[(size_t)brow * DIMV + n0 + bnq];
        breg = pack8h(*reinterpret_cast<const float4*>(b),
                      *reinterpret_cast<const float4*>(b + 4));
    }

    int buf = 0;
    const int NT = DIMV / 32;
#pragma unroll 1
    for (int kt = 0; kt < NT; kt++) {
        *reinterpret_cast<uint4*>(&As[buf][arow][akq]) = areg;
        *reinterpret_cast<uint4*>(&Bs[buf][brow][bnq]) = breg;
        __syncthreads();

        if (kt + 1 < NT) {
            int k0 = (kt + 1) * 32;
            const float* a = &x[(size_t)(m0 + arow) * DIMV + k0 + akq];
            areg = pack8h(*reinterpret_cast<const float4*>(a),
                          *reinterpret_cast<const float4*>(a + 4));
            const float* b = &wq[(size_t)(k0 + brow) * DIMV + n0 + bnq];
            breg = pack8h(*reinterpret_cast<const float4*>(b),
                          *reinterpret_cast<const float4*>(b + 4));
        }

        wmma::fragment<wmma::matrix_a, 16, 16, 16, __half, wmma::row_major> af;
        wmma::fragment<wmma::matrix_b, 16, 16, 16, __half, wmma::row_major> bf;
#pragma unroll
        for (int ks = 0; ks < 2; ks++) {
            wmma::load_matrix_sync(af, &As[buf][wm * 16][ks * 16], 40);
#pragma unroll
            for (int i = 0; i < 2; i++) {
                wmma::load_matrix_sync(bf, &Bs[buf][ks * 16][wn * 32 + i * 16], 72);
                wmma::mma_sync(acc[i], af, bf, acc[i]);
            }
        }
        buf ^= 1;
    }

    __syncthreads();
    float (*Cs)[68] = (float(*)[68])smem_raw;
#pragma unroll
    for (int i = 0; i < 2; i++)
        wmma::store_matrix_sync(&Cs[wm * 16][wn * 32 + i * 16], acc[i], 68,
                                wmma::mem_row_major);
    __syncthreads();

    const float scale = 0.99999500003749981f;
    int trow = tid >> 2;
    int tc0  = (tid & 3) * 16;
    float4 fo[4];
#pragma unroll
    for (int j = 0; j < 4; j++) {
        float4 f = *reinterpret_cast<const float4*>(&Cs[trow][tc0 + j * 4]);
        f.x *= scale; f.y *= scale; f.z *= scale; f.w *= scale;
        fo[j] = f;
    }
    uint4 hq0 = pack8h(fo[0], fo[1]);
    uint4 hq1 = pack8h(fo[2], fo[3]);
    __half* qh = &g_qh[(size_t)(m0 + trow) * DIMV + n0 + tc0];
    *reinterpret_cast<uint4*>(qh)     = hq0;
    *reinterpret_cast<uint4*>(qh + 8) = hq1;
}

// ---------------------------------------------------------------------------
// hgemm_db: fp16 WMMA, BK=32 double-buffered, half inputs. smem 19456B.
// ---------------------------------------------------------------------------
template<int K, int NTOT>
__device__ void hgemm_db(
    const __half* __restrict__ Av, const __half* __restrict__ Bv,
    float* __restrict__ C, int m0, int n0, char* smem_raw)
{
    typedef __half AsT[64][40];
    typedef __half BsT[32][72];
    AsT* As = (AsT*)smem_raw;
    BsT* Bs = (BsT*)(smem_raw + 2 * 64 * 40 * 2);

    const int tid = threadIdx.x;
    const int w = tid >> 5;
    const int wm = w >> 1;
    const int wn = w & 1;

    const int arow = tid >> 2;
    const int akq  = (tid & 3) * 8;
    const int brow = tid >> 3;
    const int bnq  = (tid & 7) * 8;

    wmma::fragment<wmma::accumulator, 16, 16, 16, float> acc[2];
    wmma::fill_fragment(acc[0], 0.0f);
    wmma::fill_fragment(acc[1], 0.0f);

    uint4 areg = *reinterpret_cast<const uint4*>(
        Av + (size_t)(m0 + arow) * K + akq);
    uint4 breg = *reinterpret_cast<const uint4*>(
        Bv + (size_t)brow * NTOT + n0 + bnq);

    int buf = 0;
    const int NT = K / 32;
#pragma unroll 1
    for (int kt = 0; kt < NT; kt++) {
        *reinterpret_cast<uint4*>(&As[buf][arow][akq]) = areg;
        *reinterpret_cast<uint4*>(&Bs[buf][brow][bnq]) = breg;
        __syncthreads();

        if (kt + 1 < NT) {
            int k0 = (kt + 1) * 32;
            areg = *reinterpret_cast<const uint4*>(
                Av + (size_t)(m0 + arow) * K + k0 + akq);
            breg = *reinterpret_cast<const uint4*>(
                Bv + (size_t)(k0 + brow) * NTOT + n0 + bnq);
        }

        wmma::fragment<wmma::matrix_a, 16, 16, 16, __half, wmma::row_major> af;
        wmma::fragment<wmma::matrix_b, 16, 16, 16, __half, wmma::row_major> bf;
#pragma unroll
        for (int ks = 0; ks < 2; ks++) {
            wmma::load_matrix_sync(af, &As[buf][wm * 16][ks * 16], 40);
#pragma unroll
            for (int i = 0; i < 2; i++) {
                wmma::load_matrix_sync(bf, &Bs[buf][ks * 16][wn * 32 + i * 16], 72);
                wmma::mma_sync(acc[i], af, bf, acc[i]);
            }
        }
        buf ^= 1;
    }

    // NOTE: __syncthreads before smem reuse happens via grid_sync in caller
#pragma unroll
    for (int i = 0; i < 2; i++) {
        wmma::store_matrix_sync(
            &C[(size_t)(m0 + wm * 16) * NTOT + n0 + wn * 32 + i * 16],
            acc[i], NTOT, wmma::mem_row_major);
    }
}

// ---------------------------------------------------------------------------
// sim: g_sim[h][t][k] for a (head, 64-token tile). smem 40960B.
// ---------------------------------------------------------------------------
__device__ void sim_block(const float* __restrict__ keys, int b, char* smem_raw)
{
    int tid = threadIdx.x;
    int t0 = (b & 15) * 64;
    int h = b >> 4;

    float (*Ks)[NUM_KEYS] = (float(*)[NUM_KEYS])smem_raw;
    float (*Qs)[64] = (float(*)[64])(smem_raw + DIM_KEY * NUM_KEYS * 4);

    {
        const float4* kp = reinterpret_cast<const float4*>(
            keys + (size_t)((h * NUM_KEYS + tid) * 2) * DIM_KEY);
#pragma unroll
        for (int i = 0; i < 8; i++) {
            float4 f = kp[i];
            Ks[4 * i + 0][tid] = f.x;
            Ks[4 * i + 1][tid] = f.y;
            Ks[4 * i + 2][tid] = f.z;
            Ks[4 * i + 3][tid] = f.w;
        }
    }
    {
        int tl = tid & 63;
        int d0 = (tid >> 6) * 8;
        size_t off = (size_t)(t0 + tl) * QCOLS + h * DIM_KEY + d0;
        float4 f0 = *reinterpret_cast<const float4*>(g_q + off);
        float4 f1 = *reinterpret_cast<const float4*>(g_q + off + 4);
        Qs[d0 + 0][tl] = f0.x; Qs[d0 + 1][tl] = f0.y;
        Qs[d0 + 2][tl] = f0.z; Qs[d0 + 3][tl] = f0.w;
        Qs[d0 + 4][tl] = f1.x; Qs[d0 + 5][tl] = f1.y;
        Qs[d0 + 6][tl] = f1.z; Qs[d0 + 7][tl] = f1.w;
    }
    __syncthreads();

    int kg = tid & 15;
    int tg = tid >> 4;
    float acc[4][16];
#pragma unroll
    for (int i = 0; i < 4; i++)
#pragma unroll
        for (int j = 0; j < 16; j++) acc[i][j] = 0.0f;

#pragma unroll
    for (int d = 0; d < DIM_KEY; d++) {
        float4 qv = *reinterpret_cast<const float4*>(&Qs[d][tg * 4]);
        float q4[4] = {qv.x, qv.y, qv.z, qv.w};
        float kv[16];
#pragma unroll
        for (int jj = 0; jj < 4; jj++) {
            float4 kk = *reinterpret_cast<const float4*>(&Ks[d][kg * 16 + jj * 4]);
            kv[jj * 4 + 0] = kk.x; kv[jj * 4 + 1] = kk.y;
            kv[jj * 4 + 2] = kk.z; kv[jj * 4 + 3] = kk.w;
        }
#pragma unroll
        for (int i = 0; i < 4; i++)
#pragma unroll
            for (int j = 0; j < 16; j++) acc[i][j] += q4[i] * kv[j];
    }

#pragma unroll
    for (int i = 0; i < 4; i++) {
        int t = t0 + tg * 4 + i;
        float* op = g_sim + ((size_t)h * TOKENS + t) * NUM_KEYS + kg * 16;
#pragma unroll
        for (int jj = 0; jj < 4; jj++) {
            float4 f;
            f.x = acc[i][jj * 4 + 0]; f.y = acc[i][jj * 4 + 1];
            f.z = acc[i][jj * 4 + 2]; f.w = acc[i][jj * 4 + 3];
            *reinterpret_cast<float4*>(op + jj * 4) = f;
        }
    }
}

// ---------------------------------------------------------------------------
// select for one token; sS is a 256-float smem buffer.
// ---------------------------------------------------------------------------
__device__ void select_token(int t, float* sS, float (*v0s)[TOPK],
                             float (*i0s)[TOPK])
{
    int tid = threadIdx.x;
    int w = tid >> 5;
    int lane = tid & 31;

    sS[tid] = 0.0f;
    __syncthreads();

    float val[8];
    {
        const float* simrow = g_sim + ((size_t)w * TOKENS + t) * NUM_KEYS;
#pragma unroll
        for (int s = 0; s < 8; s++)
            val[s] = simrow[lane + (s << 5)];
    }

    float v0[TOPK]; int i0[TOPK];
    warp_top16(val, lane, v0, i0);

    int imax = -1, i2nd = -1, jst = 0;
#pragma unroll
    for (int j = 0; j < TOPK; j++) {
        int v = i0[j];
        if (v > imax) { i2nd = imax; imax = v; jst = j; }
        else if (v > i2nd) i2nd = v;
    }
    float spread = v0[0] - v0[TOPK - 1];
    bool fast = (float)(imax - i2nd) > spread;

    if (fast) {
        float myv = -INFINITY;
#pragma unroll
        for (int r = 0; r < TOPK; r++)
            if (lane == r) myv = v0[r];
        float mye = expf(myv - v0[0]);
        float esum = mye;
#pragma unroll
        for (int off = 16; off > 0; off >>= 1)
            esum += __shfl_xor_sync(FULLMASK, esum, off);
        if (lane < TOPK) {
            int pk = lane * TOPK + jst;
            float dv = g_D[(size_t)t * NUM_KEYS + pk];
            float g = gelu_tanh(dv) * (mye / esum);
            atomicAdd(&sS[pk], g);
        }
    } else {
        if (lane == 0) {
#pragma unroll
            for (int r = 0; r < TOPK; r++) {
                v0s[w][r] = v0[r];
                i0s[w][r] = (float)i0[r];
            }
        }
        __syncwarp();
        float val2[8];
#pragma unroll
        for (int s = 0; s < 8; s++) {
            int p = lane + (s << 5);
            val2[s] = v0s[w][p >> 4] + i0s[w][p & 15];
        }
        float scf[TOPK]; int pk[TOPK];
        warp_top16(val2, lane, scf, pk);

        float myscf = -INFINITY; int mypk = 0;
#pragma unroll
        for (int r = 0; r < TOPK; r++)
            if (lane == r) { myscf = scf[r]; mypk = pk[r]; }
        float m = scf[0];
#pragma unroll
        for (int r = 1; r < TOPK; r++) m = fmaxf(m, scf[r]);
        float mye = expf(myscf - m);
        float esum = mye;
#pragma unroll
        for (int off = 16; off > 0; off >>= 1)
            esum += __shfl_xor_sync(FULLMASK, esum, off);
        if (lane < TOPK) {
            float dv = g_D[(size_t)t * NUM_KEYS + mypk];
            float g = gelu_tanh(dv) * (mye / esum);
            atomicAdd(&sS[mypk], g);
        }
    }
    __syncthreads();

    g_Sh[(size_t)t * NUM_KEYS + tid] = __float2half_rn(sS[tid]);
}

// ---------------------------------------------------------------------------
// THE persistent kernel: all four phases, 256 CTAs x 256 threads.
// ---------------------------------------------------------------------------
__global__ void __launch_bounds__(256, 2)
peer_all(const float* __restrict__ x, const float* __restrict__ wq,
         const float* __restrict__ keys, const float* __restrict__ wdown,
         const float* __restrict__ wup, float* __restrict__ out)
{
    __shared__ __align__(16) char smem[SMEM_BYTES];
    int bid = blockIdx.x;
    int tid = threadIdx.x;

    // ---------------- Phase 1: G1 + wdown transpose ----------------
    if (bid < 64) {
        int mb = bid >> 2, nb = bid & 3;
        g1_split_gemm(x, wq, mb * 64, nb * 64, smem);
    } else if (bid < 128) {
        int b = bid - 64;
        int mb = b >> 2, nb = b & 3;
        g1_plain_gemm(x, wq, mb * 64, 256 + nb * 64, smem);
    } else {
        int b = bid - 128;
        int d0 = (b & 15) * 32;
        int e0 = (b >> 4) * 32;
        float (*t)[33] = (float(*)[33])smem;
        int tx = tid & 31, ty = tid >> 5;
#pragma unroll
        for (int i = 0; i < 4; i++)
            t[ty + i * 8][tx] = wdown[(size_t)(e0 + ty + i * 8) * DIMV + d0 + tx];
        __syncthreads();
#pragma unroll
        for (int i = 0; i < 4; i++)
            g_wdTh[(size_t)(d0 + ty + i * 8) * NUM_KEYS + e0 + tx] =
                __float2half_rn(t[tx][ty + i * 8]);
    }
    grid_sync(0);

    // ---------------- Phase 2: G2 + sim + wup convert ----------------
    if (bid < 64) {
        int mb = bid >> 2, nb = bid & 3;
        hgemm_db<DIMV, NUM_KEYS>(g_qh, g_wdTh, g_D, mb * 64, nb * 64, smem);
    } else if (bid < 192) {
        sim_block(keys, bid - 64, smem);
    } else {
        // convert wup[0:256][512] -> half: 131072 floats over 64 CTAs
        int base = (bid - 192) * 2048 + tid * 8;
#pragma unroll
        for (int r = 0; r < 2; r++) {
            int idx = base + r * 4;
            float4 f = *reinterpret_cast<const float4*>(wup + idx);
            __half2 h0 = __floats2half2_rn(f.x, f.y);
            __half2 h1 = __floats2half2_rn(f.z, f.w);
            uint2 u;
            u.x = *reinterpret_cast<unsigned*>(&h0);
            u.y = *reinterpret_cast<unsigned*>(&h1);
            *reinterpret_cast<uint2*>(&g_wupH[idx]) = u;
        }
    }
    grid_sync(1);

    // ---------------- Phase 3: select, 4 tokens per CTA ----------------
    {
        float* sS = (float*)smem;                           // 1024B
        float (*v0s)[TOPK] = (float(*)[TOPK])(smem + 1024); // 512B
        float (*i0s)[TOPK] = (float(*)[TOPK])(smem + 1536); // 512B
#pragma unroll 1
        for (int i = 0; i < 4; i++) {
            select_token(bid * 4 + i, sS, v0s, i0s);
            __syncthreads();
        }
    }
    grid_sync(2);

    // ---------------- Phase 4: out = Sh @ wupH ----------------
    if (bid < 128) {
        int mb = bid >> 3, nb = bid & 7;
        hgemm_db<NUM_KEYS, DIMV>(g_Sh, g_wupH, out, mb * 64, nb * 64, smem);
    }
}

// ---------------------------------------------------------------------------
extern "C" void kernel_launch(void* const* d_in, const int* in_sizes, int n_in,
                              void* d_out, int out_size)
{
    const float* x     = (const float*)d_in[0];
    const float* w_q   = (const float*)d_in[1];
    const float* keys  = (const float*)d_in[2];
    const float* wdown = (const float*)d_in[3];
    const float* wup   = (const float*)d_in[4];
    float* out = (float*)d_out;

    peer_all<<<NBLOCKS, 256>>>(x, w_q, keys, wdown, wup, out);
}

// round 16
// speedup vs baseline: 1.1648x; 1.1517x over previous
#include <cuda_runtime.h>
#include <cuda_fp16.h>
#include <mma.h>
#include <math.h>

using namespace nvcuda;

#define DIMV       512
#define HEADS      8
#define DIM_KEY    32
#define NUM_KEYS   256
#define QCOLS      256
#define TOPK       16
#define TOKENS     1024
#define NBLOCKS    256
#define FULLMASK   0xffffffffu

// scratch (device globals; no allocs)
__device__ __align__(16) float  g_q    [TOKENS * QCOLS];
__device__ __align__(16) __half g_qh   [TOKENS * DIMV];
__device__ __align__(16) float  g_sim  [HEADS * TOKENS * NUM_KEYS];
__device__ __align__(16) __half g_wdTh [DIMV * NUM_KEYS];
__device__ __align__(16) __half g_wupH [NUM_KEYS * DIMV];
__device__ __align__(16) __half g_keyTh[HEADS * DIM_KEY * NUM_KEYS];
__device__ __align__(16) __half g_keyTl[HEADS * DIM_KEY * NUM_KEYS];
__device__ __align__(16) float  g_D    [TOKENS * NUM_KEYS];
__device__ __align__(16) __half g_Sh   [TOKENS * NUM_KEYS];

// software grid barrier state (self-resetting; zero-init at module load)
__device__ volatile unsigned g_cnt[4];
__device__ volatile unsigned g_ack[4];

__device__ __forceinline__ void grid_sync(int k) {
    __syncthreads();
    if (threadIdx.x == 0) {
        __threadfence();
        atomicAdd((unsigned*)&g_cnt[k], 1u);
        while (g_cnt[k] < NBLOCKS) __nanosleep(64);
        __threadfence();
        unsigned a = atomicAdd((unsigned*)&g_ack[k], 1u);
        if (a == NBLOCKS - 1) {
            g_cnt[k] = 0;
            __threadfence();
            g_ack[k] = 0;
        }
    }
    __syncthreads();
}

// ---------------------------------------------------------------------------
// helpers
// ---------------------------------------------------------------------------
__device__ __forceinline__ uint4 pack8h(float4 f0, float4 f1) {
    __half2 h0 = __floats2half2_rn(f0.x, f0.y);
    __half2 h1 = __floats2half2_rn(f0.z, f0.w);
    __half2 h2 = __floats2half2_rn(f1.x, f1.y);
    __half2 h3 = __floats2half2_rn(f1.z, f1.w);
    uint4 u;
    u.x = *reinterpret_cast<unsigned*>(&h0);
    u.y = *reinterpret_cast<unsigned*>(&h1);
    u.z = *reinterpret_cast<unsigned*>(&h2);
    u.w = *reinterpret_cast<unsigned*>(&h3);
    return u;
}

__device__ __forceinline__ void split8(const float* p, uint4& hi, uint4& lo) {
    float4 f0 = *reinterpret_cast<const float4*>(p);
    float4 f1 = *reinterpret_cast<const float4*>(p + 4);
    float v[8] = {f0.x, f0.y, f0.z, f0.w, f1.x, f1.y, f1.z, f1.w};
    __align__(16) __half h[8];
    __align__(16) __half l[8];
#pragma unroll
    for (int i = 0; i < 8; i++) {
        h[i] = __float2half_rn(v[i]);
        l[i] = __float2half_rn(v[i] - __half2float(h[i]));
    }
    hi = *reinterpret_cast<uint4*>(h);
    lo = *reinterpret_cast<uint4*>(l);
}

__device__ __forceinline__ float gelu_tanh(float x) {
    float x3 = x * x * x;
    float t = tanhf(0.7978845608028654f * (x + 0.044715f * x3));
    return 0.5f * x * (1.0f + t);
}

__device__ __forceinline__ void warp_top16(float* val, int lane,
                                           float* out_v, int* out_i)
{
#pragma unroll
    for (int r = 0; r < TOPK; r++) {
        float bv = val[0]; int bs = 0;
#pragma unroll
        for (int s = 1; s < 8; s++)
            if (val[s] > bv) { bv = val[s]; bs = s; }
        int bp = lane + (bs << 5);
#pragma unroll
        for (int off = 16; off > 0; off >>= 1) {
            float ov = __shfl_xor_sync(FULLMASK, bv, off);
            int   op = __shfl_xor_sync(FULLMASK, bp, off);
            if (ov > bv || (ov == bv && op < bp)) { bv = ov; bp = op; }
        }
        out_v[r] = bv;
        out_i[r] = bp;
        if ((bp & 31) == lane) {
            int ws = bp >> 5;
#pragma unroll
            for (int s = 0; s < 8; s++)
                if (s == ws) val[s] = -INFINITY;
        }
    }
}

#define SMEM_BYTES 40960

// ---------------------------------------------------------------------------
// G1a: split fp16 GEMM (xh*wh + xh*wl + xl*wh) for q cols 0..255.
// ---------------------------------------------------------------------------
__device__ void g1_split_gemm(
    const float* __restrict__ x, const float* __restrict__ wq,
    int m0, int n0, char* smem_raw)
{
    typedef __half A_t[64][40];
    typedef __half B_t[32][72];
    A_t* Ah = (A_t*)smem_raw;
    A_t* Al = (A_t*)(smem_raw + 10240);
    B_t* Bh = (B_t*)(smem_raw + 20480);
    B_t* Bl = (B_t*)(smem_raw + 29696);

    const int tid = threadIdx.x;
    const int w = tid >> 5;
    const int wm = w >> 1;
    const int wn = w & 1;

    const int arow = tid >> 2;
    const int akq  = (tid & 3) * 8;
    const int brow = tid >> 3;
    const int bnq  = (tid & 7) * 8;

    wmma::fragment<wmma::accumulator, 16, 16, 16, float> acc[2];
    wmma::fill_fragment(acc[0], 0.0f);
    wmma::fill_fragment(acc[1], 0.0f);

    uint4 ah, al, bh, bl;
    split8(&x [(size_t)(m0 + arow) * DIMV + akq], ah, al);
    split8(&wq[(size_t)brow * DIMV + n0 + bnq], bh, bl);

    int buf = 0;
    const int NT = DIMV / 32;
#pragma unroll 1
    for (int kt = 0; kt < NT; kt++) {
        *reinterpret_cast<uint4*>(&Ah[buf][arow][akq]) = ah;
        *reinterpret_cast<uint4*>(&Al[buf][arow][akq]) = al;
        *reinterpret_cast<uint4*>(&Bh[buf][brow][bnq]) = bh;
        *reinterpret_cast<uint4*>(&Bl[buf][brow][bnq]) = bl;
        __syncthreads();

        if (kt + 1 < NT) {
            int k0 = (kt + 1) * 32;
            split8(&x [(size_t)(m0 + arow) * DIMV + k0 + akq], ah, al);
            split8(&wq[(size_t)(k0 + brow) * DIMV + n0 + bnq], bh, bl);
        }

        wmma::fragment<wmma::matrix_a, 16, 16, 16, __half, wmma::row_major> afh, afl;
        wmma::fragment<wmma::matrix_b, 16, 16, 16, __half, wmma::row_major> bfh, bfl;
#pragma unroll
        for (int ks = 0; ks < 2; ks++) {
            wmma::load_matrix_sync(afh, &Ah[buf][wm * 16][ks * 16], 40);
            wmma::load_matrix_sync(afl, &Al[buf][wm * 16][ks * 16], 40);
#pragma unroll
            for (int i = 0; i < 2; i++) {
                wmma::load_matrix_sync(bfh, &Bh[buf][ks * 16][wn * 32 + i * 16], 72);
                wmma::load_matrix_sync(bfl, &Bl[buf][ks * 16][wn * 32 + i * 16], 72);
                wmma::mma_sync(acc[i], afh, bfh, acc[i]);
                wmma::mma_sync(acc[i], afh, bfl, acc[i]);
                wmma::mma_sync(acc[i], afl, bfh, acc[i]);
            }
        }
        buf ^= 1;
    }

    __syncthreads();
    float (*Cs)[68] = (float(*)[68])smem_raw;
#pragma unroll
    for (int i = 0; i < 2; i++)
        wmma::store_matrix_sync(&Cs[wm * 16][wn * 32 + i * 16], acc[i], 68,
                                wmma::mem_row_major);
    __syncthreads();

    const float scale = 0.99999500003749981f;
    int trow = tid >> 2;
    int tc0  = (tid & 3) * 16;
    float4 fo[4];
#pragma unroll
    for (int j = 0; j < 4; j++) {
        float4 f = *reinterpret_cast<const float4*>(&Cs[trow][tc0 + j * 4]);
        f.x *= scale; f.y *= scale; f.z *= scale; f.w *= scale;
        fo[j] = f;
        *reinterpret_cast<float4*>(
            &g_q[(size_t)(m0 + trow) * QCOLS + n0 + tc0 + j * 4]) = f;
    }
    uint4 hq0 = pack8h(fo[0], fo[1]);
    uint4 hq1 = pack8h(fo[2], fo[3]);
    __half* qh = &g_qh[(size_t)(m0 + trow) * DIMV + n0 + tc0];
    *reinterpret_cast<uint4*>(qh)     = hq0;
    *reinterpret_cast<uint4*>(qh + 8) = hq1;
}

// ---------------------------------------------------------------------------
// G1b: plain fp16 GEMM for q cols 256..511 -> g_qh only.
// ---------------------------------------------------------------------------
__device__ void g1_plain_gemm(
    const float* __restrict__ x, const float* __restrict__ wq,
    int m0, int n0, char* smem_raw)
{
    typedef __half AsT[64][40];
    typedef __half BsT[32][72];
    AsT* As = (AsT*)smem_raw;
    BsT* Bs = (BsT*)(smem_raw + 2 * 64 * 40 * 2);

    const int tid = threadIdx.x;
    const int w = tid >> 5;
    const int wm = w >> 1;
    const int wn = w & 1;

    const int arow = tid >> 2;
    const int akq  = (tid & 3) * 8;
    const int brow = tid >> 3;
    const int bnq  = (tid & 7) * 8;

    wmma::fragment<wmma::accumulator, 16, 16, 16, float> acc[2];
    wmma::fill_fragment(acc[0], 0.0f);
    wmma::fill_fragment(acc[1], 0.0f);

    uint4 areg, breg;
    {
        const float* a = &x[(size_t)(m0 + arow) * DIMV + akq];
        areg = pack8h(*reinterpret_cast<const float4*>(a),
                      *reinterpret_cast<const float4*>(a + 4));
        const float* b = &wq[(size_t)brow * DIMV + n0 + bnq];
        breg = pack8h(*reinterpret_cast<const float4*>(b),
                      *reinterpret_cast<const float4*>(b + 4));
    }

    int buf = 0;
    const int NT = DIMV / 32;
#pragma unroll 1
    for (int kt = 0; kt < NT; kt++) {
        *reinterpret_cast<uint4*>(&As[buf][arow][akq]) = areg;
        *reinterpret_cast<uint4*>(&Bs[buf][brow][bnq]) = breg;
        __syncthreads();

        if (kt + 1 < NT) {
            int k0 = (kt + 1) * 32;
            const float* a = &x[(size_t)(m0 + arow) * DIMV + k0 + akq];
            areg = pack8h(*reinterpret_cast<const float4*>(a),
                          *reinterpret_cast<const float4*>(a + 4));
            const float* b = &wq[(size_t)(k0 + brow) * DIMV + n0 + bnq];
            breg = pack8h(*reinterpret_cast<const float4*>(b),
                          *reinterpret_cast<const float4*>(b + 4));
        }

        wmma::fragment<wmma::matrix_a, 16, 16, 16, __half, wmma::row_major> af;
        wmma::fragment<wmma::matrix_b, 16, 16, 16, __half, wmma::row_major> bf;
#pragma unroll
        for (int ks = 0; ks < 2; ks++) {
            wmma::load_matrix_sync(af, &As[buf][wm * 16][ks * 16], 40);
#pragma unroll
            for (int i = 0; i < 2; i++) {
                wmma::load_matrix_sync(bf, &Bs[buf][ks * 16][wn * 32 + i * 16], 72);
                wmma::mma_sync(acc[i], af, bf, acc[i]);
            }
        }
        buf ^= 1;
    }

    __syncthreads();
    float (*Cs)[68] = (float(*)[68])smem_raw;
#pragma unroll
    for (int i = 0; i < 2; i++)
        wmma::store_matrix_sync(&Cs[wm * 16][wn * 32 + i * 16], acc[i], 68,
                                wmma::mem_row_major);
    __syncthreads();

    const float scale = 0.99999500003749981f;
    int trow = tid >> 2;
    int tc0  = (tid & 3) * 16;
    float4 fo[4];
#pragma unroll
    for (int j = 0; j < 4; j++) {
        float4 f = *reinterpret_cast<const float4*>(&Cs[trow][tc0 + j * 4]);
        f.x *= scale; f.y *= scale; f.z *= scale; f.w *= scale;
        fo[j] = f;
    }
    uint4 hq0 = pack8h(fo[0], fo[1]);
    uint4 hq1 = pack8h(fo[2], fo[3]);
    __half* qh = &g_qh[(size_t)(m0 + trow) * DIMV + n0 + tc0];
    *reinterpret_cast<uint4*>(qh)     = hq0;
    *reinterpret_cast<uint4*>(qh + 8) = hq1;
}

// ---------------------------------------------------------------------------
// hgemm_db: fp16 WMMA, BK=32 double-buffered, half inputs.
// ---------------------------------------------------------------------------
template<int K, int NTOT>
__device__ void hgemm_db(
    const __half* __restrict__ Av, const __half* __restrict__ Bv,
    float* __restrict__ C, int m0, int n0, char* smem_raw)
{
    typedef __half AsT[64][40];
    typedef __half BsT[32][72];
    AsT* As = (AsT*)smem_raw;
    BsT* Bs = (BsT*)(smem_raw + 2 * 64 * 40 * 2);

    const int tid = threadIdx.x;
    const int w = tid >> 5;
    const int wm = w >> 1;
    const int wn = w & 1;

    const int arow = tid >> 2;
    const int akq  = (tid & 3) * 8;
    const int brow = tid >> 3;
    const int bnq  = (tid & 7) * 8;

    wmma::fragment<wmma::accumulator, 16, 16, 16, float> acc[2];
    wmma::fill_fragment(acc[0], 0.0f);
    wmma::fill_fragment(acc[1], 0.0f);

    uint4 areg = *reinterpret_cast<const uint4*>(
        Av + (size_t)(m0 + arow) * K + akq);
    uint4 breg = *reinterpret_cast<const uint4*>(
        Bv + (size_t)brow * NTOT + n0 + bnq);

    int buf = 0;
    const int NT = K / 32;
#pragma unroll 1
    for (int kt = 0; kt < NT; kt++) {
        *reinterpret_cast<uint4*>(&As[buf][arow][akq]) = areg;
        *reinterpret_cast<uint4*>(&Bs[buf][brow][bnq]) = breg;
        __syncthreads();

        if (kt + 1 < NT) {
            int k0 = (kt + 1) * 32;
            areg = *reinterpret_cast<const uint4*>(
                Av + (size_t)(m0 + arow) * K + k0 + akq);
            breg = *reinterpret_cast<const uint4*>(
                Bv + (size_t)(k0 + brow) * NTOT + n0 + bnq);
        }

        wmma::fragment<wmma::matrix_a, 16, 16, 16, __half, wmma::row_major> af;
        wmma::fragment<wmma::matrix_b, 16, 16, 16, __half, wmma::row_major> bf;
#pragma unroll
        for (int ks = 0; ks < 2; ks++) {
            wmma::load_matrix_sync(af, &As[buf][wm * 16][ks * 16], 40);
#pragma unroll
            for (int i = 0; i < 2; i++) {
                wmma::load_matrix_sync(bf, &Bs[buf][ks * 16][wn * 32 + i * 16], 72);
                wmma::mma_sync(acc[i], af, bf, acc[i]);
            }
        }
        buf ^= 1;
    }

#pragma unroll
    for (int i = 0; i < 2; i++) {
        wmma::store_matrix_sync(
            &C[(size_t)(m0 + wm * 16) * NTOT + n0 + wn * 32 + i * 16],
            acc[i], NTOT, wmma::mem_row_major);
    }
}

// ---------------------------------------------------------------------------
// sim via split HMMA: for task (h, nb, mq) compute 4 tiles of
// sim[h][m0:m0+64][n0:n0+64] = q_exact @ keysT via qh*kh + qh*kl + ql*kh.
// smem: Ah[64][40] Al (5120 each) + Bh[32][72] Bl (4608 each) = 19456B
// ---------------------------------------------------------------------------
__device__ void sim_mma(int task, char* smem_raw)
{
    int h  = task >> 4;            // 0..7
    int nb = (task >> 2) & 3;      // 0..3
    int mq = task & 3;             // 0..3
    int n0 = nb * 64;

    __half (*Ah)[40] = (__half(*)[40])smem_raw;
    __half (*Al)[40] = (__half(*)[40])(smem_raw + 5120);
    __half (*Bh)[72] = (__half(*)[72])(smem_raw + 10240);
    __half (*Bl)[72] = (__half(*)[72])(smem_raw + 14848);

    const int tid = threadIdx.x;
    const int w = tid >> 5;
    const int wm = w >> 1;
    const int wn = w & 1;

    // stage B (keysT slice) once: 32 rows x 64 cols, hi+lo
    {
        int brow = tid >> 3;            // 0..31
        int bcq  = (tid & 7) * 8;       // 0..56
        size_t off = (size_t)(h * DIM_KEY + brow) * NUM_KEYS + n0 + bcq;
        *reinterpret_cast<uint4*>(&Bh[brow][bcq]) =
            *reinterpret_cast<const uint4*>(g_keyTh + off);
        *reinterpret_cast<uint4*>(&Bl[brow][bcq]) =
            *reinterpret_cast<const uint4*>(g_keyTl + off);
    }

    const int arow = tid >> 2;          // 0..63
    const int acq  = (tid & 3) * 8;     // 0,8,16,24

#pragma unroll 1
    for (int mi = 0; mi < 4; mi++) {
        int m0 = (mq * 4 + mi) * 64;

        // stage A: q rows m0..m0+63, head cols (fp32 -> split)
        uint4 hi, lo;
        split8(&g_q[(size_t)(m0 + arow) * QCOLS + h * DIM_KEY + acq], hi, lo);
        *reinterpret_cast<uint4*>(&Ah[arow][acq]) = hi;
        *reinterpret_cast<uint4*>(&Al[arow][acq]) = lo;
        __syncthreads();

        wmma::fragment<wmma::accumulator, 16, 16, 16, float> acc[2];
        wmma::fill_fragment(acc[0], 0.0f);
        wmma::fill_fragment(acc[1], 0.0f);

        wmma::fragment<wmma::matrix_a, 16, 16, 16, __half, wmma::row_major> afh, afl;
        wmma::fragment<wmma::matrix_b, 16, 16, 16, __half, wmma::row_major> bfh, bfl;
#pragma unroll
        for (int ks = 0; ks < 2; ks++) {
            wmma::load_matrix_sync(afh, &Ah[wm * 16][ks * 16], 40);
            wmma::load_matrix_sync(afl, &Al[wm * 16][ks * 16], 40);
#pragma unroll
            for (int i = 0; i < 2; i++) {
                wmma::load_matrix_sync(bfh, &Bh[ks * 16][wn * 32 + i * 16], 72);
                wmma::load_matrix_sync(bfl, &Bl[ks * 16][wn * 32 + i * 16], 72);
                wmma::mma_sync(acc[i], afh, bfh, acc[i]);
                wmma::mma_sync(acc[i], afh, bfl, acc[i]);
                wmma::mma_sync(acc[i], afl, bfh, acc[i]);
            }
        }

#pragma unroll
        for (int i = 0; i < 2; i++) {
            wmma::store_matrix_sync(
                &g_sim[((size_t)h * TOKENS + m0 + wm * 16) * NUM_KEYS
                       + n0 + wn * 32 + i * 16],
                acc[i], NUM_KEYS, wmma::mem_row_major);
        }
        __syncthreads();   // before restaging A
    }
}

// ---------------------------------------------------------------------------
// select for one token.
// ---------------------------------------------------------------------------
__device__ void select_token(int t, float* sS, float (*v0s)[TOPK],
                             float (*i0s)[TOPK])
{
    int tid = threadIdx.x;
    int w = tid >> 5;
    int lane = tid & 31;

    sS[tid] = 0.0f;
    __syncthreads();

    float val[8];
    {
        const float* simrow = g_sim + ((size_t)w * TOKENS + t) * NUM_KEYS;
#pragma unroll
        for (int s = 0; s < 8; s++)
            val[s] = simrow[lane + (s << 5)];
    }

    float v0[TOPK]; int i0[TOPK];
    warp_top16(val, lane, v0, i0);

    int imax = -1, i2nd = -1, jst = 0;
#pragma unroll
    for (int j = 0; j < TOPK; j++) {
        int v = i0[j];
        if (v > imax) { i2nd = imax; imax = v; jst = j; }
        else if (v > i2nd) i2nd = v;
    }
    float spread = v0[0] - v0[TOPK - 1];
    bool fast = (float)(imax - i2nd) > spread;

    if (fast) {
        float myv = -INFINITY;
#pragma unroll
        for (int r = 0; r < TOPK; r++)
            if (lane == r) myv = v0[r];
        float mye = expf(myv - v0[0]);
        float esum = mye;
#pragma unroll
        for (int off = 16; off > 0; off >>= 1)
            esum += __shfl_xor_sync(FULLMASK, esum, off);
        if (lane < TOPK) {
            int pk = lane * TOPK + jst;
            float dv = g_D[(size_t)t * NUM_KEYS + pk];
            float g = gelu_tanh(dv) * (mye / esum);
            atomicAdd(&sS[pk], g);
        }
    } else {
        if (lane == 0) {
#pragma unroll
            for (int r = 0; r < TOPK; r++) {
                v0s[w][r] = v0[r];
                i0s[w][r] = (float)i0[r];
            }
        }
        __syncwarp();
        float val2[8];
#pragma unroll
        for (int s = 0; s < 8; s++) {
            int p = lane + (s << 5);
            val2[s] = v0s[w][p >> 4] + i0s[w][p & 15];
        }
        float scf[TOPK]; int pk[TOPK];
        warp_top16(val2, lane, scf, pk);

        float myscf = -INFINITY; int mypk = 0;
#pragma unroll
        for (int r = 0; r < TOPK; r++)
            if (lane == r) { myscf = scf[r]; mypk = pk[r]; }
        float m = scf[0];
#pragma unroll
        for (int r = 1; r < TOPK; r++) m = fmaxf(m, scf[r]);
        float mye = expf(myscf - m);
        float esum = mye;
#pragma unroll
        for (int off = 16; off > 0; off >>= 1)
            esum += __shfl_xor_sync(FULLMASK, esum, off);
        if (lane < TOPK) {
            float dv = g_D[(size_t)t * NUM_KEYS + mypk];
            float g = gelu_tanh(dv) * (mye / esum);
            atomicAdd(&sS[mypk], g);
        }
    }
    __syncthreads();

    g_Sh[(size_t)t * NUM_KEYS + tid] = __float2half_rn(sS[tid]);
}

// ---------------------------------------------------------------------------
// THE persistent kernel: all four phases, 256 CTAs x 256 threads.
// ---------------------------------------------------------------------------
__global__ void __launch_bounds__(256, 2)
peer_all(const float* __restrict__ x, const float* __restrict__ wq,
         const float* __restrict__ keys, const float* __restrict__ wdown,
         const float* __restrict__ wup, float* __restrict__ out)
{
    __shared__ __align__(16) char smem[SMEM_BYTES];
    int bid = blockIdx.x;
    int tid = threadIdx.x;

    // ---------------- Phase 1 ----------------
    if (bid < 64) {
        int mb = bid >> 2, nb = bid & 3;
        g1_split_gemm(x, wq, mb * 64, nb * 64, smem);
    } else if (bid < 128) {
        int b = bid - 64;
        int mb = b >> 2, nb = b & 3;
        g1_plain_gemm(x, wq, mb * 64, 256 + nb * 64, smem);
    } else if (bid < 192) {
        // wdown transpose -> half: 128 tiles over 64 CTAs (2 each)
        float (*t)[33] = (float(*)[33])smem;
        int tx = tid & 31, ty = tid >> 5;
#pragma unroll 1
        for (int r = 0; r < 2; r++) {
            int b = (bid - 128) + r * 64;
            int d0 = (b & 15) * 32;
            int e0 = (b >> 4) * 32;
            __syncthreads();
#pragma unroll
            for (int i = 0; i < 4; i++)
                t[ty + i * 8][tx] = wdown[(size_t)(e0 + ty + i * 8) * DIMV + d0 + tx];
            __syncthreads();
#pragma unroll
            for (int i = 0; i < 4; i++)
                g_wdTh[(size_t)(d0 + ty + i * 8) * NUM_KEYS + e0 + tx] =
                    __float2half_rn(t[tx][ty + i * 8]);
        }
    } else {
        // keys transpose + split: 64 CTAs, (h, 32-key chunk)
        int b = bid - 192;
        int h = b >> 3;
        int k0 = (b & 7) * 32;
        float (*t)[33] = (float(*)[33])smem;
        int tx = tid & 31, ty = tid >> 5;
#pragma unroll
        for (int i = 0; i < 4; i++)
            t[ty + i * 8][tx] =
                keys[((size_t)(h * NUM_KEYS + k0 + ty + i * 8) * 2) * DIM_KEY + tx];
        __syncthreads();
#pragma unroll
        for (int i = 0; i < 4; i++) {
            int d = ty + i * 8;
            float v = t[tx][d];
            __half hi = __float2half_rn(v);
            __half lo = __float2half_rn(v - __half2float(hi));
            size_t off = (size_t)(h * DIM_KEY + d) * NUM_KEYS + k0 + tx;
            g_keyTh[off] = hi;
            g_keyTl[off] = lo;
        }
    }
    grid_sync(0);

    // ---------------- Phase 2: G2 + sim-MMA + wup convert ----------------
    if (bid < 64) {
        int mb = bid >> 2, nb = bid & 3;
        hgemm_db<DIMV, NUM_KEYS>(g_qh, g_wdTh, g_D, mb * 64, nb * 64, smem);
    } else if (bid < 192) {
        sim_mma(bid - 64, smem);
    } else {
        int base = (bid - 192) * 2048 + tid * 8;
#pragma unroll
        for (int r = 0; r < 2; r++) {
            int idx = base + r * 4;
            float4 f = *reinterpret_cast<const float4*>(wup + idx);
            __half2 h0 = __floats2half2_rn(f.x, f.y);
            __half2 h1 = __floats2half2_rn(f.z, f.w);
            uint2 u;
            u.x = *reinterpret_cast<unsigned*>(&h0);
            u.y = *reinterpret_cast<unsigned*>(&h1);
            *reinterpret_cast<uint2*>(&g_wupH[idx]) = u;
        }
    }
    grid_sync(1);

    // ---------------- Phase 3: select, 4 tokens per CTA ----------------
    {
        float* sS = (float*)smem;
        float (*v0s)[TOPK] = (float(*)[TOPK])(smem + 1024);
        float (*i0s)[TOPK] = (float(*)[TOPK])(smem + 1536);
#pragma unroll 1
        for (int i = 0; i < 4; i++) {
            select_token(bid * 4 + i, sS, v0s, i0s);
            __syncthreads();
        }
    }
    grid_sync(2);

    // ---------------- Phase 4: out = Sh @ wupH ----------------
    if (bid < 128) {
        int mb = bid >> 3, nb = bid & 7;
        hgemm_db<NUM_KEYS, DIMV>(g_Sh, g_wupH, out, mb * 64, nb * 64, smem);
    }
}

// ---------------------------------------------------------------------------
extern "C" void kernel_launch(void* const* d_in, const int* in_sizes, int n_in,
                              void* d_out, int out_size)
{
    const float* x     = (const float*)d_in[0];
    const float* w_q   = (const float*)d_in[1];
    const float* keys  = (const float*)d_in[2];
    const float* wdown = (const float*)d_in[3];
    const float* wup   = (const float*)d_in[4];
    float* out = (float*)d_out;

    peer_all<<<NBLOCKS, 256>>>(x, w_q, keys, wdown, wup, out);
}

// round 17
// speedup vs baseline: 1.2003x; 1.0305x over previous
#include <cuda_runtime.h>
#include <cuda_fp16.h>
#include <mma.h>
#include <math.h>

using namespace nvcuda;

#define DIMV       512
#define HEADS      8
#define DIM_KEY    32
#define NUM_KEYS   256
#define QCOLS      256
#define TOPK       16
#define TOKENS     1024
#define NBLOCKS    256
#define FULLMASK   0xffffffffu

// scratch (device globals; no allocs)
__device__ __align__(16) float  g_qp0  [TOKENS * QCOLS];   // q cols 0-255, k 0-255
__device__ __align__(16) float  g_qp1  [TOKENS * QCOLS];   // q cols 0-255, k 256-511
__device__ __align__(16) __half g_qh   [TOKENS * DIMV];    // cols 256-511 valid
__device__ __align__(16) float  g_sim  [HEADS * TOKENS * NUM_KEYS];
__device__ __align__(16) __half g_wdTh [DIMV * NUM_KEYS];
__device__ __align__(16) __half g_wupH [NUM_KEYS * DIMV];
__device__ __align__(16) __half g_keyTh[HEADS * DIM_KEY * NUM_KEYS];
__device__ __align__(16) __half g_keyTl[HEADS * DIM_KEY * NUM_KEYS];
__device__ __align__(16) float  g_Dp0  [TOKENS * NUM_KEYS];
__device__ __align__(16) float  g_Dp1  [TOKENS * NUM_KEYS];
__device__ __align__(16) __half g_Sh   [TOKENS * NUM_KEYS];

// software grid barrier (self-resetting)
__device__ volatile unsigned g_cnt[4];
__device__ volatile unsigned g_ack[4];

__device__ __forceinline__ void grid_sync(int k) {
    __syncthreads();
    if (threadIdx.x == 0) {
        __threadfence();
        atomicAdd((unsigned*)&g_cnt[k], 1u);
        while (g_cnt[k] < NBLOCKS) __nanosleep(64);
        __threadfence();
        unsigned a = atomicAdd((unsigned*)&g_ack[k], 1u);
        if (a == NBLOCKS - 1) {
            g_cnt[k] = 0;
            __threadfence();
            g_ack[k] = 0;
        }
    }
    __syncthreads();
}

// ---------------------------------------------------------------------------
// helpers
// ---------------------------------------------------------------------------
__device__ __forceinline__ uint4 pack8h(float4 f0, float4 f1) {
    __half2 h0 = __floats2half2_rn(f0.x, f0.y);
    __half2 h1 = __floats2half2_rn(f0.z, f0.w);
    __half2 h2 = __floats2half2_rn(f1.x, f1.y);
    __half2 h3 = __floats2half2_rn(f1.z, f1.w);
    uint4 u;
    u.x = *reinterpret_cast<unsigned*>(&h0);
    u.y = *reinterpret_cast<unsigned*>(&h1);
    u.z = *reinterpret_cast<unsigned*>(&h2);
    u.w = *reinterpret_cast<unsigned*>(&h3);
    return u;
}

__device__ __forceinline__ void split8(const float* p, uint4& hi, uint4& lo) {
    float4 f0 = *reinterpret_cast<const float4*>(p);
    float4 f1 = *reinterpret_cast<const float4*>(p + 4);
    float v[8] = {f0.x, f0.y, f0.z, f0.w, f1.x, f1.y, f1.z, f1.w};
    __align__(16) __half h[8];
    __align__(16) __half l[8];
#pragma unroll
    for (int i = 0; i < 8; i++) {
        h[i] = __float2half_rn(v[i]);
        l[i] = __float2half_rn(v[i] - __half2float(h[i]));
    }
    hi = *reinterpret_cast<uint4*>(h);
    lo = *reinterpret_cast<uint4*>(l);
}

// split of (p0 + p1)
__device__ __forceinline__ void split8sum(const float* p0, const float* p1,
                                          uint4& hi, uint4& lo) {
    float4 a0 = *reinterpret_cast<const float4*>(p0);
    float4 a1 = *reinterpret_cast<const float4*>(p0 + 4);
    float4 b0 = *reinterpret_cast<const float4*>(p1);
    float4 b1 = *reinterpret_cast<const float4*>(p1 + 4);
    float v[8] = {a0.x + b0.x, a0.y + b0.y, a0.z + b0.z, a0.w + b0.w,
                  a1.x + b1.x, a1.y + b1.y, a1.z + b1.z, a1.w + b1.w};
    __align__(16) __half h[8];
    __align__(16) __half l[8];
#pragma unroll
    for (int i = 0; i < 8; i++) {
        h[i] = __float2half_rn(v[i]);
        l[i] = __float2half_rn(v[i] - __half2float(h[i]));
    }
    hi = *reinterpret_cast<uint4*>(h);
    lo = *reinterpret_cast<uint4*>(l);
}

__device__ __forceinline__ float gelu_tanh(float x) {
    float x3 = x * x * x;
    float t = tanhf(0.7978845608028654f * (x + 0.044715f * x3));
    return 0.5f * x * (1.0f + t);
}

__device__ __forceinline__ void warp_top16(float* val, int lane,
                                           float* out_v, int* out_i)
{
#pragma unroll
    for (int r = 0; r < TOPK; r++) {
        float bv = val[0]; int bs = 0;
#pragma unroll
        for (int s = 1; s < 8; s++)
            if (val[s] > bv) { bv = val[s]; bs = s; }
        int bp = lane + (bs << 5);
#pragma unroll
        for (int off = 16; off > 0; off >>= 1) {
            float ov = __shfl_xor_sync(FULLMASK, bv, off);
            int   op = __shfl_xor_sync(FULLMASK, bp, off);
            if (ov > bv || (ov == bv && op < bp)) { bv = ov; bp = op; }
        }
        out_v[r] = bv;
        out_i[r] = bp;
        if ((bp & 31) == lane) {
            int ws = bp >> 5;
#pragma unroll
            for (int s = 0; s < 8; s++)
                if (s == ws) val[s] = -INFINITY;
        }
    }
}

#define SMEM_BYTES 40960

// ---------------------------------------------------------------------------
// g1_split_k: split fp16 GEMM over a K-half (NT=8). Writes fp32 partial only.
// x pre-offset by koff, wq pre-offset by koff*DIMV.
// ---------------------------------------------------------------------------
__device__ void g1_split_k(
    const float* __restrict__ x, const float* __restrict__ wq,
    float* __restrict__ outp, int m0, int n0, char* smem_raw)
{
    typedef __half A_t[64][40];
    typedef __half B_t[32][72];
    A_t* Ah = (A_t*)smem_raw;
    A_t* Al = (A_t*)(smem_raw + 10240);
    B_t* Bh = (B_t*)(smem_raw + 20480);
    B_t* Bl = (B_t*)(smem_raw + 29696);

    const int tid = threadIdx.x;
    const int w = tid >> 5;
    const int wm = w >> 1;
    const int wn = w & 1;

    const int arow = tid >> 2;
    const int akq  = (tid & 3) * 8;
    const int brow = tid >> 3;
    const int bnq  = (tid & 7) * 8;

    wmma::fragment<wmma::accumulator, 16, 16, 16, float> acc[2];
    wmma::fill_fragment(acc[0], 0.0f);
    wmma::fill_fragment(acc[1], 0.0f);

    uint4 ah, al, bh, bl;
    split8(&x [(size_t)(m0 + arow) * DIMV + akq], ah, al);
    split8(&wq[(size_t)brow * DIMV + n0 + bnq], bh, bl);

    int buf = 0;
    const int NT = 8;
#pragma unroll 1
    for (int kt = 0; kt < NT; kt++) {
        *reinterpret_cast<uint4*>(&Ah[buf][arow][akq]) = ah;
        *reinterpret_cast<uint4*>(&Al[buf][arow][akq]) = al;
        *reinterpret_cast<uint4*>(&Bh[buf][brow][bnq]) = bh;
        *reinterpret_cast<uint4*>(&Bl[buf][brow][bnq]) = bl;
        __syncthreads();

        if (kt + 1 < NT) {
            int k0 = (kt + 1) * 32;
            split8(&x [(size_t)(m0 + arow) * DIMV + k0 + akq], ah, al);
            split8(&wq[(size_t)(k0 + brow) * DIMV + n0 + bnq], bh, bl);
        }

        wmma::fragment<wmma::matrix_a, 16, 16, 16, __half, wmma::row_major> afh, afl;
        wmma::fragment<wmma::matrix_b, 16, 16, 16, __half, wmma::row_major> bfh, bfl;
#pragma unroll
        for (int ks = 0; ks < 2; ks++) {
            wmma::load_matrix_sync(afh, &Ah[buf][wm * 16][ks * 16], 40);
            wmma::load_matrix_sync(afl, &Al[buf][wm * 16][ks * 16], 40);
#pragma unroll
            for (int i = 0; i < 2; i++) {
                wmma::load_matrix_sync(bfh, &Bh[buf][ks * 16][wn * 32 + i * 16], 72);
                wmma::load_matrix_sync(bfl, &Bl[buf][ks * 16][wn * 32 + i * 16], 72);
                wmma::mma_sync(acc[i], afh, bfh, acc[i]);
                wmma::mma_sync(acc[i], afh, bfl, acc[i]);
                wmma::mma_sync(acc[i], afl, bfh, acc[i]);
            }
        }
        buf ^= 1;
    }

    __syncthreads();
    float (*Cs)[68] = (float(*)[68])smem_raw;
#pragma unroll
    for (int i = 0; i < 2; i++)
        wmma::store_matrix_sync(&Cs[wm * 16][wn * 32 + i * 16], acc[i], 68,
                                wmma::mem_row_major);
    __syncthreads();

    const float scale = 0.99999500003749981f;
    int trow = tid >> 2;
    int tc0  = (tid & 3) * 16;
#pragma unroll
    for (int j = 0; j < 4; j++) {
        float4 f = *reinterpret_cast<const float4*>(&Cs[trow][tc0 + j * 4]);
        f.x *= scale; f.y *= scale; f.z *= scale; f.w *= scale;
        *reinterpret_cast<float4*>(
            &outp[(size_t)(m0 + trow) * QCOLS + n0 + tc0 + j * 4]) = f;
    }
}

// ---------------------------------------------------------------------------
// g1_plain: plain fp16 GEMM for q cols 256..511 -> g_qh.
// ---------------------------------------------------------------------------
__device__ void g1_plain_gemm(
    const float* __restrict__ x, const float* __restrict__ wq,
    int m0, int n0, char* smem_raw)
{
    typedef __half AsT[64][40];
    typedef __half BsT[32][72];
    AsT* As = (AsT*)smem_raw;
    BsT* Bs = (BsT*)(smem_raw + 2 * 64 * 40 * 2);

    const int tid = threadIdx.x;
    const int w = tid >> 5;
    const int wm = w >> 1;
    const int wn = w & 1;

    const int arow = tid >> 2;
    const int akq  = (tid & 3) * 8;
    const int brow = tid >> 3;
    const int bnq  = (tid & 7) * 8;

    wmma::fragment<wmma::accumulator, 16, 16, 16, float> acc[2];
    wmma::fill_fragment(acc[0], 0.0f);
    wmma::fill_fragment(acc[1], 0.0f);

    uint4 areg, breg;
    {
        const float* a = &x[(size_t)(m0 + arow) * DIMV + akq];
        areg = pack8h(*reinterpret_cast<const float4*>(a),
                      *reinterpret_cast<const float4*>(a + 4));
        const float* b = &wq[(size_t)brow * DIMV + n0 + bnq];
        breg = pack8h(*reinterpret_cast<const float4*>(b),
                      *reinterpret_cast<const float4*>(b + 4));
    }

    int buf = 0;
    const int NT = DIMV / 32;
#pragma unroll 1
    for (int kt = 0; kt < NT; kt++) {
        *reinterpret_cast<uint4*>(&As[buf][arow][akq]) = areg;
        *reinterpret_cast<uint4*>(&Bs[buf][brow][bnq]) = breg;
        __syncthreads();

        if (kt + 1 < NT) {
            int k0 = (kt + 1) * 32;
            const float* a = &x[(size_t)(m0 + arow) * DIMV + k0 + akq];
            areg = pack8h(*reinterpret_cast<const float4*>(a),
                          *reinterpret_cast<const float4*>(a + 4));
            const float* b = &wq[(size_t)(k0 + brow) * DIMV + n0 + bnq];
            breg = pack8h(*reinterpret_cast<const float4*>(b),
                          *reinterpret_cast<const float4*>(b + 4));
        }

        wmma::fragment<wmma::matrix_a, 16, 16, 16, __half, wmma::row_major> af;
        wmma::fragment<wmma::matrix_b, 16, 16, 16, __half, wmma::row_major> bf;
#pragma unroll
        for (int ks = 0; ks < 2; ks++) {
            wmma::load_matrix_sync(af, &As[buf][wm * 16][ks * 16], 40);
#pragma unroll
            for (int i = 0; i < 2; i++) {
                wmma::load_matrix_sync(bf, &Bs[buf][ks * 16][wn * 32 + i * 16], 72);
                wmma::mma_sync(acc[i], af, bf, acc[i]);
            }
        }
        buf ^= 1;
    }

    __syncthreads();
    float (*Cs)[68] = (float(*)[68])smem_raw;
#pragma unroll
    for (int i = 0; i < 2; i++)
        wmma::store_matrix_sync(&Cs[wm * 16][wn * 32 + i * 16], acc[i], 68,
                                wmma::mem_row_major);
    __syncthreads();

    const float scale = 0.99999500003749981f;
    int trow = tid >> 2;
    int tc0  = (tid & 3) * 16;
    float4 fo[4];
#pragma unroll
    for (int j = 0; j < 4; j++) {
        float4 f = *reinterpret_cast<const float4*>(&Cs[trow][tc0 + j * 4]);
        f.x *= scale; f.y *= scale; f.z *= scale; f.w *= scale;
        fo[j] = f;
    }
    uint4 hq0 = pack8h(fo[0], fo[1]);
    uint4 hq1 = pack8h(fo[2], fo[3]);
    __half* qh = &g_qh[(size_t)(m0 + trow) * DIMV + n0 + tc0];
    *reinterpret_cast<uint4*>(qh)     = hq0;
    *reinterpret_cast<uint4*>(qh + 8) = hq1;
}

// ---------------------------------------------------------------------------
// hgemm_db_h: fp16 WMMA, BK=32 double-buffered. Av/Bv pre-offset; NT k-tiles.
// ---------------------------------------------------------------------------
template<int NT, int NTOT, int ALDA>
__device__ void hgemm_db_h(
    const __half* __restrict__ Av, const __half* __restrict__ Bv,
    float* __restrict__ C, int m0, int n0, char* smem_raw)
{
    typedef __half AsT[64][40];
    typedef __half BsT[32][72];
    AsT* As = (AsT*)smem_raw;
    BsT* Bs = (BsT*)(smem_raw + 2 * 64 * 40 * 2);

    const int tid = threadIdx.x;
    const int w = tid >> 5;
    const int wm = w >> 1;
    const int wn = w & 1;

    const int arow = tid >> 2;
    const int akq  = (tid & 3) * 8;
    const int brow = tid >> 3;
    const int bnq  = (tid & 7) * 8;

    wmma::fragment<wmma::accumulator, 16, 16, 16, float> acc[2];
    wmma::fill_fragment(acc[0], 0.0f);
    wmma::fill_fragment(acc[1], 0.0f);

    uint4 areg = *reinterpret_cast<const uint4*>(
        Av + (size_t)(m0 + arow) * ALDA + akq);
    uint4 breg = *reinterpret_cast<const uint4*>(
        Bv + (size_t)brow * NTOT + n0 + bnq);

    int buf = 0;
#pragma unroll 1
    for (int kt = 0; kt < NT; kt++) {
        *reinterpret_cast<uint4*>(&As[buf][arow][akq]) = areg;
        *reinterpret_cast<uint4*>(&Bs[buf][brow][bnq]) = breg;
        __syncthreads();

        if (kt + 1 < NT) {
            int k0 = (kt + 1) * 32;
            areg = *reinterpret_cast<const uint4*>(
                Av + (size_t)(m0 + arow) * ALDA + k0 + akq);
            breg = *reinterpret_cast<const uint4*>(
                Bv + (size_t)(k0 + brow) * NTOT + n0 + bnq);
        }

        wmma::fragment<wmma::matrix_a, 16, 16, 16, __half, wmma::row_major> af;
        wmma::fragment<wmma::matrix_b, 16, 16, 16, __half, wmma::row_major> bf;
#pragma unroll
        for (int ks = 0; ks < 2; ks++) {
            wmma::load_matrix_sync(af, &As[buf][wm * 16][ks * 16], 40);
#pragma unroll
            for (int i = 0; i < 2; i++) {
                wmma::load_matrix_sync(bf, &Bs[buf][ks * 16][wn * 32 + i * 16], 72);
                wmma::mma_sync(acc[i], af, bf, acc[i]);
            }
        }
        buf ^= 1;
    }

#pragma unroll
    for (int i = 0; i < 2; i++) {
        wmma::store_matrix_sync(
            &C[(size_t)(m0 + wm * 16) * NTOT + n0 + wn * 32 + i * 16],
            acc[i], NTOT, wmma::mem_row_major);
    }
}

// ---------------------------------------------------------------------------
// hgemm_db_dual: like above, A = half(A0 + A1) staged inline (fp32, stride QCOLS)
// ---------------------------------------------------------------------------
template<int NT, int NTOT>
__device__ void hgemm_db_dual(
    const float* __restrict__ A0, const float* __restrict__ A1,
    const __half* __restrict__ Bv,
    float* __restrict__ C, int m0, int n0, char* smem_raw)
{
    typedef __half AsT[64][40];
    typedef __half BsT[32][72];
    AsT* As = (AsT*)smem_raw;
    BsT* Bs = (BsT*)(smem_raw + 2 * 64 * 40 * 2);

    const int tid = threadIdx.x;
    const int w = tid >> 5;
    const int wm = w >> 1;
    const int wn = w & 1;

    const int arow = tid >> 2;
    const int akq  = (tid & 3) * 8;
    const int brow = tid >> 3;
    const int bnq  = (tid & 7) * 8;

    wmma::fragment<wmma::accumulator, 16, 16, 16, float> acc[2];
    wmma::fill_fragment(acc[0], 0.0f);
    wmma::fill_fragment(acc[1], 0.0f);

    auto stageA = [&](int k0) -> uint4 {
        size_t off = (size_t)(m0 + arow) * QCOLS + k0 + akq;
        float4 a0 = *reinterpret_cast<const float4*>(A0 + off);
        float4 a1 = *reinterpret_cast<const float4*>(A0 + off + 4);
        float4 b0 = *reinterpret_cast<const float4*>(A1 + off);
        float4 b1 = *reinterpret_cast<const float4*>(A1 + off + 4);
        a0.x += b0.x; a0.y += b0.y; a0.z += b0.z; a0.w += b0.w;
        a1.x += b1.x; a1.y += b1.y; a1.z += b1.z; a1.w += b1.w;
        return pack8h(a0, a1);
    };

    uint4 areg = stageA(0);
    uint4 breg = *reinterpret_cast<const uint4*>(
        Bv + (size_t)brow * NTOT + n0 + bnq);

    int buf = 0;
#pragma unroll 1
    for (int kt = 0; kt < NT; kt++) {
        *reinterpret_cast<uint4*>(&As[buf][arow][akq]) = areg;
        *reinterpret_cast<uint4*>(&Bs[buf][brow][bnq]) = breg;
        __syncthreads();

        if (kt + 1 < NT) {
            int k0 = (kt + 1) * 32;
            areg = stageA(k0);
            breg = *reinterpret_cast<const uint4*>(
                Bv + (size_t)(k0 + brow) * NTOT + n0 + bnq);
        }

        wmma::fragment<wmma::matrix_a, 16, 16, 16, __half, wmma::row_major> af;
        wmma::fragment<wmma::matrix_b, 16, 16, 16, __half, wmma::row_major> bf;
#pragma unroll
        for (int ks = 0; ks < 2; ks++) {
            wmma::load_matrix_sync(af, &As[buf][wm * 16][ks * 16], 40);
#pragma unroll
            for (int i = 0; i < 2; i++) {
                wmma::load_matrix_sync(bf, &Bs[buf][ks * 16][wn * 32 + i * 16], 72);
                wmma::mma_sync(acc[i], af, bf, acc[i]);
            }
        }
        buf ^= 1;
    }

#pragma unroll
    for (int i = 0; i < 2; i++) {
        wmma::store_matrix_sync(
            &C[(size_t)(m0 + wm * 16) * NTOT + n0 + wn * 32 + i * 16],
            acc[i], NTOT, wmma::mem_row_major);
    }
}

// ---------------------------------------------------------------------------
// sim via split HMMA; A staged from qp0+qp1.
// ---------------------------------------------------------------------------
__device__ void sim_mma(int task, char* smem_raw)
{
    int h  = task >> 4;
    int nb = (task >> 2) & 3;
    int mq = task & 3;
    int n0 = nb * 64;

    __half (*Ah)[40] = (__half(*)[40])smem_raw;
    __half (*Al)[40] = (__half(*)[40])(smem_raw + 5120);
    __half (*Bh)[72] = (__half(*)[72])(smem_raw + 10240);
    __half (*Bl)[72] = (__half(*)[72])(smem_raw + 14848);

    const int tid = threadIdx.x;
    const int w = tid >> 5;
    const int wm = w >> 1;
    const int wn = w & 1;

    {
        int brow = tid >> 3;
        int bcq  = (tid & 7) * 8;
        size_t off = (size_t)(h * DIM_KEY + brow) * NUM_KEYS + n0 + bcq;
        *reinterpret_cast<uint4*>(&Bh[brow][bcq]) =
            *reinterpret_cast<const uint4*>(g_keyTh + off);
        *reinterpret_cast<uint4*>(&Bl[brow][bcq]) =
            *reinterpret_cast<const uint4*>(g_keyTl + off);
    }

    const int arow = tid >> 2;
    const int acq  = (tid & 3) * 8;

#pragma unroll 1
    for (int mi = 0; mi < 4; mi++) {
        int m0 = (mq * 4 + mi) * 64;

        uint4 hi, lo;
        size_t off = (size_t)(m0 + arow) * QCOLS + h * DIM_KEY + acq;
        split8sum(g_qp0 + off, g_qp1 + off, hi, lo);
        *reinterpret_cast<uint4*>(&Ah[arow][acq]) = hi;
        *reinterpret_cast<uint4*>(&Al[arow][acq]) = lo;
        __syncthreads();

        wmma::fragment<wmma::accumulator, 16, 16, 16, float> acc[2];
        wmma::fill_fragment(acc[0], 0.0f);
        wmma::fill_fragment(acc[1], 0.0f);

        wmma::fragment<wmma::matrix_a, 16, 16, 16, __half, wmma::row_major> afh, afl;
        wmma::fragment<wmma::matrix_b, 16, 16, 16, __half, wmma::row_major> bfh, bfl;
#pragma unroll
        for (int ks = 0; ks < 2; ks++) {
            wmma::load_matrix_sync(afh, &Ah[wm * 16][ks * 16], 40);
            wmma::load_matrix_sync(afl, &Al[wm * 16][ks * 16], 40);
#pragma unroll
            for (int i = 0; i < 2; i++) {
                wmma::load_matrix_sync(bfh, &Bh[ks * 16][wn * 32 + i * 16], 72);
                wmma::load_matrix_sync(bfl, &Bl[ks * 16][wn * 32 + i * 16], 72);
                wmma::mma_sync(acc[i], afh, bfh, acc[i]);
                wmma::mma_sync(acc[i], afh, bfl, acc[i]);
                wmma::mma_sync(acc[i], afl, bfh, acc[i]);
            }
        }

#pragma unroll
        for (int i = 0; i < 2; i++) {
            wmma::store_matrix_sync(
                &g_sim[((size_t)h * TOKENS + m0 + wm * 16) * NUM_KEYS
                       + n0 + wn * 32 + i * 16],
                acc[i], NUM_KEYS, wmma::mem_row_major);
        }
        __syncthreads();
    }
}

// ---------------------------------------------------------------------------
// select for one token. D = Dp0 + Dp1 at gather points.
// ---------------------------------------------------------------------------
__device__ void select_token(int t, float* sS, float (*v0s)[TOPK],
                             float (*i0s)[TOPK])
{
    int tid = threadIdx.x;
    int w = tid >> 5;
    int lane = tid & 31;

    sS[tid] = 0.0f;
    __syncthreads();

    float val[8];
    {
        const float* simrow = g_sim + ((size_t)w * TOKENS + t) * NUM_KEYS;
#pragma unroll
        for (int s = 0; s < 8; s++)
            val[s] = simrow[lane + (s << 5)];
    }

    float v0[TOPK]; int i0[TOPK];
    warp_top16(val, lane, v0, i0);

    int imax = -1, i2nd = -1, jst = 0;
#pragma unroll
    for (int j = 0; j < TOPK; j++) {
        int v = i0[j];
        if (v > imax) { i2nd = imax; imax = v; jst = j; }
        else if (v > i2nd) i2nd = v;
    }
    float spread = v0[0] - v0[TOPK - 1];
    bool fast = (float)(imax - i2nd) > spread;

    if (fast) {
        float myv = -INFINITY;
#pragma unroll
        for (int r = 0; r < TOPK; r++)
            if (lane == r) myv = v0[r];
        float mye = expf(myv - v0[0]);
        float esum = mye;
#pragma unroll
        for (int off = 16; off > 0; off >>= 1)
            esum += __shfl_xor_sync(FULLMASK, esum, off);
        if (lane < TOPK) {
            int pk = lane * TOPK + jst;
            size_t di = (size_t)t * NUM_KEYS + pk;
            float dv = g_Dp0[di] + g_Dp1[di];
            float g = gelu_tanh(dv) * (mye / esum);
            atomicAdd(&sS[pk], g);
        }
    } else {
        if (lane == 0) {
#pragma unroll
            for (int r = 0; r < TOPK; r++) {
                v0s[w][r] = v0[r];
                i0s[w][r] = (float)i0[r];
            }
        }
        __syncwarp();
        float val2[8];
#pragma unroll
        for (int s = 0; s < 8; s++) {
            int p = lane + (s << 5);
            val2[s] = v0s[w][p >> 4] + i0s[w][p & 15];
        }
        float scf[TOPK]; int pk[TOPK];
        warp_top16(val2, lane, scf, pk);

        float myscf = -INFINITY; int mypk = 0;
#pragma unroll
        for (int r = 0; r < TOPK; r++)
            if (lane == r) { myscf = scf[r]; mypk = pk[r]; }
        float m = scf[0];
#pragma unroll
        for (int r = 1; r < TOPK; r++) m = fmaxf(m, scf[r]);
        float mye = expf(myscf - m);
        float esum = mye;
#pragma unroll
        for (int off = 16; off > 0; off >>= 1)
            esum += __shfl_xor_sync(FULLMASK, esum, off);
        if (lane < TOPK) {
            size_t di = (size_t)t * NUM_KEYS + mypk;
            float dv = g_Dp0[di] + g_Dp1[di];
            float g = gelu_tanh(dv) * (mye / esum);
            atomicAdd(&sS[mypk], g);
        }
    }
    __syncthreads();

    g_Sh[(size_t)t * NUM_KEYS + tid] = __float2half_rn(sS[tid]);
}

// ---------------------------------------------------------------------------
// THE persistent kernel.
// ---------------------------------------------------------------------------
__global__ void __launch_bounds__(256, 2)
peer_all(const float* __restrict__ x, const float* __restrict__ wq,
         const float* __restrict__ keys, const float* __restrict__ wdown,
         const float* __restrict__ wup, float* __restrict__ out)
{
    __shared__ __align__(16) char smem[SMEM_BYTES];
    int bid = blockIdx.x;
    int tid = threadIdx.x;

    // ---------------- Phase 1 ----------------
    if (bid < 128) {
        // G1a split-K=2: tile 0..63, sp 0/1
        int tile = bid >> 1;
        int sp = bid & 1;
        int mb = tile >> 2, nb = tile & 3;
        int koff = sp * 256;
        float* outp = sp ? g_qp1 : g_qp0;
        g1_split_k(x + koff, wq + (size_t)koff * DIMV, outp,
                   mb * 64, nb * 64, smem);
    } else if (bid < 192) {
        int b = bid - 128;
        g1_plain_gemm(x, wq, (b >> 2) * 64, 256 + (b & 3) * 64, smem);
    } else if (bid < 224) {
        // wdown transpose: 128 tiles over 32 CTAs (4 each)
        float (*t)[33] = (float(*)[33])smem;
        int tx = tid & 31, ty = tid >> 5;
#pragma unroll 1
        for (int r = 0; r < 4; r++) {
            int b = (bid - 192) * 4 + r;
            int d0 = (b & 15) * 32;
            int e0 = (b >> 4) * 32;
            __syncthreads();
#pragma unroll
            for (int i = 0; i < 4; i++)
                t[ty + i * 8][tx] = wdown[(size_t)(e0 + ty + i * 8) * DIMV + d0 + tx];
            __syncthreads();
#pragma unroll
            for (int i = 0; i < 4; i++)
                g_wdTh[(size_t)(d0 + ty + i * 8) * NUM_KEYS + e0 + tx] =
                    __float2half_rn(t[tx][ty + i * 8]);
        }
    } else if (bid < 240) {
        // keys transpose + split: 64 jobs over 16 CTAs (4 each)
        float (*t)[33] = (float(*)[33])smem;
        int tx = tid & 31, ty = tid >> 5;
#pragma unroll 1
        for (int r = 0; r < 4; r++) {
            int b = (bid - 224) * 4 + r;
            int h = b >> 3;
            int k0 = (b & 7) * 32;
            __syncthreads();
#pragma unroll
            for (int i = 0; i < 4; i++)
                t[ty + i * 8][tx] =
                    keys[((size_t)(h * NUM_KEYS + k0 + ty + i * 8) * 2) * DIM_KEY + tx];
            __syncthreads();
#pragma unroll
            for (int i = 0; i < 4; i++) {
                int d = ty + i * 8;
                float v = t[tx][d];
                __half hi = __float2half_rn(v);
                __half lo = __float2half_rn(v - __half2float(hi));
                size_t off = (size_t)(h * DIM_KEY + d) * NUM_KEYS + k0 + tx;
                g_keyTh[off] = hi;
                g_keyTl[off] = lo;
            }
        }
    } else {
        // wup convert: 32768 float4 over 16 CTAs
        int cta = bid - 240;
#pragma unroll
        for (int r = 0; r < 8; r++) {
            int i4 = cta * 2048 + r * 256 + tid;
            float4 f = reinterpret_cast<const float4*>(wup)[i4];
            __half2 h0 = __floats2half2_rn(f.x, f.y);
            __half2 h1 = __floats2half2_rn(f.z, f.w);
            uint2 u;
            u.x = *reinterpret_cast<unsigned*>(&h0);
            u.y = *reinterpret_cast<unsigned*>(&h1);
            reinterpret_cast<uint2*>(g_wupH)[i4] = u;
        }
    }
    grid_sync(0);

    // ---------------- Phase 2: G2 split-K + sim-MMA ----------------
    if (bid < 128) {
        int tile = bid >> 1;
        int sp = bid & 1;
        int mb = tile >> 2, nb = tile & 3;
        if (sp == 0) {
            hgemm_db_dual<8, NUM_KEYS>(g_qp0, g_qp1, g_wdTh,
                                       g_Dp0, mb * 64, nb * 64, smem);
        } else {
            hgemm_db_h<8, NUM_KEYS, DIMV>(
                g_qh + 256, g_wdTh + (size_t)256 * NUM_KEYS,
                g_Dp1, mb * 64, nb * 64, smem);
        }
    } else {
        sim_mma(bid - 128, smem);
    }
    grid_sync(1);

    // ---------------- Phase 3: select, 4 tokens per CTA ----------------
    {
        float* sS = (float*)smem;
        float (*v0s)[TOPK] = (float(*)[TOPK])(smem + 1024);
        float (*i0s)[TOPK] = (float(*)[TOPK])(smem + 1536);
#pragma unroll 1
        for (int i = 0; i < 4; i++) {
            select_token(bid * 4 + i, sS, v0s, i0s);
            __syncthreads();
        }
    }
    grid_sync(2);

    // ---------------- Phase 4: out = Sh @ wupH ----------------
    if (bid < 128) {
        int mb = bid >> 3, nb = bid & 7;
        hgemm_db_h<8, DIMV, NUM_KEYS>(g_Sh, g_wupH, out, mb * 64, nb * 64, smem);
    }
}

// ---------------------------------------------------------------------------
extern "C" void kernel_launch(void* const* d_in, const int* in_sizes, int n_in,
                              void* d_out, int out_size)
{
    const float* x     = (const float*)d_in[0];
    const float* w_q   = (const float*)d_in[1];
    const float* keys  = (const float*)d_in[2];
    const float* wdown = (const float*)d_in[3];
    const float* wup   = (const float*)d_in[4];
    float* out = (float*)d_out;

    peer_all<<<NBLOCKS, 256>>>(x, w_q, keys, wdown, wup, out);
}